// round 2
// baseline (speedup 1.0000x reference)
#include <cuda_runtime.h>
#include <stdint.h>

#define N_NODES 100000
#define N_EDGES 3200000
#define NFEAT   512
#define NHID    256
#define NCLASS  16
#define KSTEPS  10

// ---------------- scratch (device globals: no allocation allowed) ----------
__device__ float g_hid[(size_t)N_NODES * NHID];     // 102.4 MB
__device__ float g_hA[(size_t)N_NODES * NCLASS];    // 6.4 MB
__device__ float g_hB[(size_t)N_NODES * NCLASS];    // 6.4 MB
__device__ int   g_cnt_row[N_NODES];
__device__ int   g_cnt_col[N_NODES];
__device__ int   g_colptr[N_NODES];
__device__ int   g_fill[N_NODES];
__device__ float g_s[N_NODES];
__device__ int   g_csr_row[N_EDGES];                // 12.8 MB

// ---------------- graph preprocessing --------------------------------------
__global__ void k_init_counts() {
    int i = blockIdx.x * blockDim.x + threadIdx.x;
    if (i < N_NODES) { g_cnt_row[i] = 0; g_cnt_col[i] = 0; }
}

__global__ void k_hist(const int* __restrict__ ei) {
    int e = blockIdx.x * blockDim.x + threadIdx.x;
    if (e < N_EDGES) {
        atomicAdd(&g_cnt_row[ei[e]], 1);
        atomicAdd(&g_cnt_col[ei[N_EDGES + e]], 1);
    }
}

__global__ void k_compute_s() {
    int i = blockIdx.x * blockDim.x + threadIdx.x;
    if (i < N_NODES) {
        int d = g_cnt_row[i];
        g_s[i] = (d > 0) ? rsqrtf((float)d) : 0.0f;
    }
}

// single-block chunked exclusive scan of g_cnt_col -> g_colptr (+ copy g_fill)
__global__ void k_scan() {
    __shared__ int wsum[32];
    __shared__ int carry;
    const int tid = threadIdx.x, lane = tid & 31, wid = tid >> 5;
    if (tid == 0) carry = 0;
    __syncthreads();
    for (int base = 0; base < N_NODES; base += 1024) {
        int i = base + tid;
        int v = (i < N_NODES) ? g_cnt_col[i] : 0;
        int x = v;
        #pragma unroll
        for (int o = 1; o < 32; o <<= 1) {
            int y = __shfl_up_sync(0xffffffffu, x, o);
            if (lane >= o) x += y;
        }
        if (lane == 31) wsum[wid] = x;
        __syncthreads();
        if (wid == 0) {
            int w = wsum[lane];
            #pragma unroll
            for (int o = 1; o < 32; o <<= 1) {
                int y = __shfl_up_sync(0xffffffffu, w, o);
                if (lane >= o) w += y;
            }
            wsum[lane] = w;
        }
        __syncthreads();
        int off  = carry + (wid ? wsum[wid - 1] : 0);
        int excl = off + x - v;
        if (i < N_NODES) { g_colptr[i] = excl; g_fill[i] = excl; }
        int total = wsum[31];
        __syncthreads();
        if (tid == 0) carry += total;
        __syncthreads();
    }
}

__global__ void k_csr_fill(const int* __restrict__ ei) {
    int e = blockIdx.x * blockDim.x + threadIdx.x;
    if (e < N_EDGES) {
        int r = ei[e];
        int c = ei[N_EDGES + e];
        int pos = atomicAdd(&g_fill[c], 1);
        g_csr_row[pos] = r;
    }
}

// ---- GEMM1: hid = relu(x @ W1 + b1), fp32 SIMT 128x128x8, double-buffered -
__global__ void __launch_bounds__(256) k_gemm1(const float* __restrict__ A,
                                               const float* __restrict__ W,
                                               const float* __restrict__ bias) {
    __shared__ float As[2][8][128];
    __shared__ float Bs[2][8][128];
    const int tid = threadIdx.x;
    const int tx = tid & 15, ty = tid >> 4;           // 16x16 thread grid
    const int bm = blockIdx.y * 128, bn = blockIdx.x * 128;
    const int arow = tid >> 1, acol = (tid & 1) * 4;  // A staging: 128 rows x 8 cols
    const int brow = tid >> 5, bcol = (tid & 31) * 4; // B staging: 8 rows x 128 cols
    const bool a_ok = (bm + arow) < N_NODES;
    const size_t a_base = (size_t)(bm + arow) * NFEAT + acol;

    float acc[8][8];
    #pragma unroll
    for (int i = 0; i < 8; i++)
        #pragma unroll
        for (int j = 0; j < 8; j++) acc[i][j] = 0.0f;

    // preload tile 0 into buffer 0
    {
        float4 a4 = make_float4(0.f, 0.f, 0.f, 0.f);
        if (a_ok) a4 = *(const float4*)(A + a_base);
        As[0][acol + 0][arow] = a4.x;
        As[0][acol + 1][arow] = a4.y;
        As[0][acol + 2][arow] = a4.z;
        As[0][acol + 3][arow] = a4.w;
        *(float4*)&Bs[0][brow][bcol] =
            *(const float4*)(W + (size_t)brow * NHID + bn + bcol);
    }
    __syncthreads();

    for (int k0 = 0; k0 < NFEAT; k0 += 8) {
        const int buf = (k0 >> 3) & 1;
        const bool have_next = (k0 + 8) < NFEAT;
        float4 a4n = make_float4(0.f, 0.f, 0.f, 0.f);
        float4 b4n;
        if (have_next) {
            if (a_ok) a4n = *(const float4*)(A + a_base + k0 + 8);
            b4n = *(const float4*)(W + (size_t)(k0 + 8 + brow) * NHID + bn + bcol);
        }
        #pragma unroll
        for (int k = 0; k < 8; k++) {
            float ra[8], rb[8];
            *(float4*)(ra)     = *(float4*)&As[buf][k][ty * 4];
            *(float4*)(ra + 4) = *(float4*)&As[buf][k][64 + ty * 4];
            *(float4*)(rb)     = *(float4*)&Bs[buf][k][tx * 4];
            *(float4*)(rb + 4) = *(float4*)&Bs[buf][k][64 + tx * 4];
            #pragma unroll
            for (int i = 0; i < 8; i++)
                #pragma unroll
                for (int j = 0; j < 8; j++) acc[i][j] += ra[i] * rb[j];
        }
        if (have_next) {
            const int nb = buf ^ 1;
            As[nb][acol + 0][arow] = a4n.x;
            As[nb][acol + 1][arow] = a4n.y;
            As[nb][acol + 2][arow] = a4n.z;
            As[nb][acol + 3][arow] = a4n.w;
            *(float4*)&Bs[nb][brow][bcol] = b4n;
        }
        __syncthreads();
    }

    #pragma unroll
    for (int i = 0; i < 8; i++) {
        int r = bm + ((i < 4) ? (ty * 4 + i) : (64 + ty * 4 + (i - 4)));
        if (r < N_NODES) {
            #pragma unroll
            for (int jj = 0; jj < 2; jj++) {
                int cbase = bn + jj * 64 + tx * 4;
                float4 b4 = *(const float4*)(bias + cbase);
                float4 o;
                o.x = fmaxf(acc[i][jj * 4 + 0] + b4.x, 0.0f);
                o.y = fmaxf(acc[i][jj * 4 + 1] + b4.y, 0.0f);
                o.z = fmaxf(acc[i][jj * 4 + 2] + b4.z, 0.0f);
                o.w = fmaxf(acc[i][jj * 4 + 3] + b4.w, 0.0f);
                *(float4*)&g_hid[(size_t)r * NHID + cbase] = o;
            }
        }
    }
}

// ---------------- GEMM2: h = hid @ W2 + b2; hA = h; out = gamma0*h ---------
__global__ void __launch_bounds__(256) k_gemm2(const float* __restrict__ W2,
                                               const float* __restrict__ b2,
                                               const float* __restrict__ gamma,
                                               float* __restrict__ out) {
    __shared__ float sW[NHID * NCLASS];  // 16 KB
    const int tid = threadIdx.x;
    for (int i = tid; i < NHID * NCLASS; i += 256) sW[i] = W2[i];
    __syncthreads();
    const int node = blockIdx.x * 16 + (tid >> 4);   // 6250 blocks * 16 = 100000 exact
    const int c = tid & 15;
    const float4* hr = (const float4*)(g_hid + (size_t)node * NHID);
    float acc = 0.0f;
    #pragma unroll 8
    for (int kk = 0; kk < NHID / 4; kk++) {
        float4 h4 = hr[kk];
        int k = kk * 4;
        acc += h4.x * sW[(k + 0) * NCLASS + c];
        acc += h4.y * sW[(k + 1) * NCLASS + c];
        acc += h4.z * sW[(k + 2) * NCLASS + c];
        acc += h4.w * sW[(k + 3) * NCLASS + c];
    }
    float v = acc + b2[c];
    g_hA[(size_t)node * NCLASS + c] = v;
    out[(size_t)node * NCLASS + c] = gamma[0] * v;
}

// ---------------- propagation: one warp per node, CSR gather, no atomics ---
// h_new[v] = s[v] * sum_{e: col(e)=v} s[row(e)] * h_in[row(e)];  out += g_k*h_new
__global__ void __launch_bounds__(256) k_prop(const float* __restrict__ gamma,
                                              float* __restrict__ out,
                                              int k, int flip) {
    const int gwarp = (blockIdx.x * blockDim.x + threadIdx.x) >> 5;
    if (gwarp >= N_NODES) return;
    const float* __restrict__ hin  = flip ? g_hB : g_hA;
    float* __restrict__       hout = flip ? g_hA : g_hB;
    const int lane = threadIdx.x & 31;
    const int c = lane & 15;         // class
    const int half = lane >> 4;      // edge slot (0/1)
    const int start = g_colptr[gwarp];
    const int len = g_cnt_col[gwarp];
    const int* __restrict__ rows = g_csr_row + start;

    float acc = 0.0f;
    int i = half;
    for (; i + 2 < len; i += 4) {    // 2 edges per slot-iteration (4 across warp)
        int r0 = rows[i];
        int r1 = rows[i + 2];
        acc += g_s[r0] * hin[(size_t)r0 * NCLASS + c];
        acc += g_s[r1] * hin[(size_t)r1 * NCLASS + c];
    }
    if (i < len) {
        int r = rows[i];
        acc += g_s[r] * hin[(size_t)r * NCLASS + c];
    }
    acc += __shfl_down_sync(0xffffffffu, acc, 16);
    if (half == 0) {
        float hv = g_s[gwarp] * acc;
        hout[(size_t)gwarp * NCLASS + c] = hv;
        out[(size_t)gwarp * NCLASS + c] += gamma[k] * hv;
    }
}

// ---------------- launch ----------------------------------------------------
extern "C" void kernel_launch(void* const* d_in, const int* in_sizes, int n_in,
                              void* d_out, int out_size) {
    const float* x     = (const float*)d_in[0];
    const int*   ei    = (const int*)  d_in[1];
    const float* W1    = (const float*)d_in[2];
    const float* b1    = (const float*)d_in[3];
    const float* W2    = (const float*)d_in[4];
    const float* b2    = (const float*)d_in[5];
    const float* gamma = (const float*)d_in[6];
    float* out = (float*)d_out;

    // graph preprocessing (rebuilt every call -> deterministic per-launch work)
    k_init_counts<<<(N_NODES + 255) / 256, 256>>>();
    k_hist<<<(N_EDGES + 255) / 256, 256>>>(ei);
    k_compute_s<<<(N_NODES + 255) / 256, 256>>>();
    k_scan<<<1, 1024>>>();
    k_csr_fill<<<(N_EDGES + 255) / 256, 256>>>(ei);

    // MLP
    dim3 g1(NHID / 128, (N_NODES + 127) / 128);
    k_gemm1<<<g1, 256>>>(x, W1, b1);
    k_gemm2<<<N_NODES / 16, 256>>>(W2, b2, gamma, out);

    // K propagation steps (ping-pong hA/hB)
    const int prop_blocks = (N_NODES * 32 + 255) / 256;
    for (int k = 1; k <= KSTEPS; k++)
        k_prop<<<prop_blocks, 256>>>(gamma, out, k, (k - 1) & 1);
}

// round 5
// speedup vs baseline: 1.4754x; 1.4754x over previous
#include <cuda_runtime.h>
#include <cuda_bf16.h>
#include <stdint.h>

#define N_NODES 100000
#define N_EDGES 3200000
#define NFEAT   512
#define NHID    256
#define NCLASS  16
#define KSTEPS  10
#define NBLK_SCAN 98   // ceil(100000/1024)

// ---------------- scratch (device globals: no allocation allowed) ----------
__device__ float g_hid[(size_t)N_NODES * NHID];     // 102.4 MB
__device__ float g_hA[(size_t)N_NODES * NCLASS];    // 6.4 MB
__device__ float g_hB[(size_t)N_NODES * NCLASS];    // 6.4 MB
__device__ int   g_cnt_row[N_NODES];
__device__ int   g_cnt_col[N_NODES];
__device__ int   g_colptr[N_NODES];
__device__ int   g_fill[N_NODES];
__device__ float g_s[N_NODES];
__device__ int   g_csr_row[N_EDGES];                // 12.8 MB
__device__ int   g_bsum[NBLK_SCAN];
__device__ int   g_boff[NBLK_SCAN];
// W1 transposed + split to bf16 hi/lo: [NHID=256 rows][NFEAT=512 cols] K-major
__device__ uint4 g_W4hi[16384];                     // 256 KB
__device__ uint4 g_W4lo[16384];                     // 256 KB

// ---------------- graph preprocessing --------------------------------------
__global__ void k_init_counts() {
    int i = blockIdx.x * blockDim.x + threadIdx.x;
    if (i < N_NODES) { g_cnt_row[i] = 0; g_cnt_col[i] = 0; }
}

__global__ void k_hist(const int* __restrict__ ei) {
    int e = blockIdx.x * blockDim.x + threadIdx.x;
    if (e < N_EDGES) {
        atomicAdd(&g_cnt_row[ei[e]], 1);
        atomicAdd(&g_cnt_col[ei[N_EDGES + e]], 1);
    }
}

__global__ void k_compute_s() {
    int i = blockIdx.x * blockDim.x + threadIdx.x;
    if (i < N_NODES) {
        int d = g_cnt_row[i];
        g_s[i] = (d > 0) ? rsqrtf((float)d) : 0.0f;
    }
}

// parallel scan, stage 1: per-block exclusive scan + block sums
__global__ void __launch_bounds__(1024) k_scan1() {
    __shared__ int wsum[32];
    const int tid = threadIdx.x, lane = tid & 31, wid = tid >> 5;
    int i = blockIdx.x * 1024 + tid;
    int v = (i < N_NODES) ? g_cnt_col[i] : 0;
    int x = v;
    #pragma unroll
    for (int o = 1; o < 32; o <<= 1) {
        int y = __shfl_up_sync(0xffffffffu, x, o);
        if (lane >= o) x += y;
    }
    if (lane == 31) wsum[wid] = x;
    __syncthreads();
    if (wid == 0) {
        int w = wsum[lane];
        #pragma unroll
        for (int o = 1; o < 32; o <<= 1) {
            int y = __shfl_up_sync(0xffffffffu, w, o);
            if (lane >= o) w += y;
        }
        wsum[lane] = w;
    }
    __syncthreads();
    int excl = (wid ? wsum[wid - 1] : 0) + x - v;
    if (i < N_NODES) g_colptr[i] = excl;
    if (tid == 1023) g_bsum[blockIdx.x] = wsum[31];
}

// stage 2: scan the 98 block sums (single small block)
__global__ void k_scan2() {
    __shared__ int s[128];
    int tid = threadIdx.x;
    int v = (tid < NBLK_SCAN) ? g_bsum[tid] : 0;
    s[tid] = v;
    __syncthreads();
    for (int o = 1; o < 128; o <<= 1) {
        int t = (tid >= o) ? s[tid - o] : 0;
        __syncthreads();
        s[tid] += t;
        __syncthreads();
    }
    if (tid < NBLK_SCAN) g_boff[tid] = s[tid] - v;
}

// stage 3: add block offsets
__global__ void k_scan3() {
    int i = blockIdx.x * blockDim.x + threadIdx.x;
    if (i < N_NODES) {
        int v = g_colptr[i] + g_boff[i >> 10];
        g_colptr[i] = v;
        g_fill[i] = v;
    }
}

__global__ void k_csr_fill(const int* __restrict__ ei) {
    int e = blockIdx.x * blockDim.x + threadIdx.x;
    if (e < N_EDGES) {
        int r = ei[e];
        int c = ei[N_EDGES + e];
        int pos = atomicAdd(&g_fill[c], 1);
        g_csr_row[pos] = r;
    }
}

// ---------------- W1 prep: transpose + bf16 hi/lo split --------------------
__global__ void k_wprep(const float* __restrict__ W1) {
    int t = blockIdx.x * blockDim.x + threadIdx.x;
    if (t >= NHID * NFEAT) return;
    int n = t >> 9;        // 0..255
    int k = t & 511;       // 0..511
    float v = W1[(size_t)k * NHID + n];
    __nv_bfloat16 h = __float2bfloat16_rn(v);
    float lo = v - __bfloat162float(h);
    ((__nv_bfloat16*)g_W4hi)[(size_t)n * NFEAT + k] = h;
    ((__nv_bfloat16*)g_W4lo)[(size_t)n * NFEAT + k] = __float2bfloat16_rn(lo);
}

// ---------------- mma.sync helpers (sm_80+ baseline, works on sm_100) ------
__device__ __forceinline__ uint32_t smem_u32(const void* p) {
    uint32_t a;
    asm("{ .reg .u64 t; cvta.to.shared.u64 t, %1; cvt.u32.u64 %0, t; }" : "=r"(a) : "l"(p));
    return a;
}
__device__ __forceinline__ void ldsm_x4(uint32_t* r, uint32_t addr) {
    asm volatile("ldmatrix.sync.aligned.m8n8.x4.shared.b16 {%0,%1,%2,%3}, [%4];"
                 : "=r"(r[0]), "=r"(r[1]), "=r"(r[2]), "=r"(r[3]) : "r"(addr));
}
__device__ __forceinline__ void ldsm_x2(uint32_t* r, uint32_t addr) {
    asm volatile("ldmatrix.sync.aligned.m8n8.x2.shared.b16 {%0,%1}, [%2];"
                 : "=r"(r[0]), "=r"(r[1]) : "r"(addr));
}
__device__ __forceinline__ void mma_bf16(float* c, const uint32_t* a, const uint32_t* b) {
    asm volatile("mma.sync.aligned.m16n8k16.row.col.f32.bf16.bf16.f32 "
                 "{%0,%1,%2,%3}, {%4,%5,%6,%7}, {%8,%9}, {%0,%1,%2,%3};"
                 : "+f"(c[0]), "+f"(c[1]), "+f"(c[2]), "+f"(c[3])
                 : "r"(a[0]), "r"(a[1]), "r"(a[2]), "r"(a[3]), "r"(b[0]), "r"(b[1]));
}

// ---- GEMM1: hid = relu(x@W1+b1), bf16x3 via mma.sync, BM=128 BN=128 BK=32 -
#define APAD 40   // row stride in bf16 elems (32 + 8 pad) -> 80B, LDSM conflict-free

__global__ void __launch_bounds__(256, 2) k_gemm1_mma(const float* __restrict__ A,
                                                      const float* __restrict__ bias) {
    __shared__ __align__(16) __nv_bfloat16 sAhi[128 * APAD];
    __shared__ __align__(16) __nv_bfloat16 sAlo[128 * APAD];
    __shared__ __align__(16) __nv_bfloat16 sWhi[128 * APAD];
    __shared__ __align__(16) __nv_bfloat16 sWlo[128 * APAD];

    const int tid = threadIdx.x;
    const int wid = tid >> 5, lane = tid & 31;
    const int warp_m = wid & 3;          // 4 warps in M, 32 rows each
    const int warp_n = wid >> 2;         // 2 warps in N, 64 cols each
    const int bm = blockIdx.y * 128;
    const int bn = blockIdx.x * 128;

    float acc[2][8][4];                  // [m16 tile][n8 tile][frag]
    #pragma unroll
    for (int mt = 0; mt < 2; mt++)
        #pragma unroll
        for (int t = 0; t < 8; t++)
            #pragma unroll
            for (int j = 0; j < 4; j++) acc[mt][t][j] = 0.0f;

    // precomputed ldmatrix smem addresses (byte offsets constant per thread)
    const int lr16 = lane & 15;
    const uint32_t a_base = smem_u32(sAhi);
    const uint32_t al_base = smem_u32(sAlo);
    const uint32_t w_base = smem_u32(sWhi);
    const uint32_t wl_base = smem_u32(sWlo);
    const uint32_t a_off = (uint32_t)(((warp_m * 32 + lr16) * APAD + (lane >> 4) * 8) * 2);
    const uint32_t b_off = (uint32_t)(((warp_n * 64 + (lr16 & 7)) * APAD + ((lr16 >> 3) * 8)) * 2);

    for (int k0 = 0; k0 < NFEAT; k0 += 32) {
        // stage A: 128 rows x 32 cols fp32 -> hi/lo bf16
        #pragma unroll
        for (int i = 0; i < 4; i++) {
            int u = i * 256 + tid;        // 0..1023
            int r = u >> 3, q = u & 7;    // row, float4 slot
            float4 v = make_float4(0.f, 0.f, 0.f, 0.f);
            if (bm + r < N_NODES)
                v = *(const float4*)(A + (size_t)(bm + r) * NFEAT + k0 + q * 4);
            __nv_bfloat16 h0 = __float2bfloat16_rn(v.x), h1 = __float2bfloat16_rn(v.y);
            __nv_bfloat16 h2 = __float2bfloat16_rn(v.z), h3 = __float2bfloat16_rn(v.w);
            uint2 ph, pl;
            ph.x = ((uint32_t)__bfloat16_as_ushort(h1) << 16) | __bfloat16_as_ushort(h0);
            ph.y = ((uint32_t)__bfloat16_as_ushort(h3) << 16) | __bfloat16_as_ushort(h2);
            __nv_bfloat16 l0 = __float2bfloat16_rn(v.x - __bfloat162float(h0));
            __nv_bfloat16 l1 = __float2bfloat16_rn(v.y - __bfloat162float(h1));
            __nv_bfloat16 l2 = __float2bfloat16_rn(v.z - __bfloat162float(h2));
            __nv_bfloat16 l3 = __float2bfloat16_rn(v.w - __bfloat162float(h3));
            pl.x = ((uint32_t)__bfloat16_as_ushort(l1) << 16) | __bfloat16_as_ushort(l0);
            pl.y = ((uint32_t)__bfloat16_as_ushort(l3) << 16) | __bfloat16_as_ushort(l2);
            *(uint2*)&sAhi[r * APAD + q * 4] = ph;
            *(uint2*)&sAlo[r * APAD + q * 4] = pl;
        }
        // stage W: 128 rows x 32 cols bf16 (hi/lo), from K-major g_W4
        #pragma unroll
        for (int i = 0; i < 2; i++) {
            int u = i * 256 + tid;        // 0..511
            int n = u >> 2, kk = u & 3;   // row, uint4 slot
            int gi = (bn + n) * 64 + (k0 >> 3) + kk;
            *(uint4*)&sWhi[n * APAD + kk * 8] = g_W4hi[gi];
            *(uint4*)&sWlo[n * APAD + kk * 8] = g_W4lo[gi];
        }
        __syncthreads();

        #pragma unroll
        for (int ks = 0; ks < 32; ks += 16) {
            uint32_t ahi[2][4], alo[2][4];
            ldsm_x4(ahi[0], a_base + a_off + ks * 2);
            ldsm_x4(ahi[1], a_base + a_off + (16 * APAD + ks) * 2);
            ldsm_x4(alo[0], al_base + a_off + ks * 2);
            ldsm_x4(alo[1], al_base + a_off + (16 * APAD + ks) * 2);
            #pragma unroll
            for (int t = 0; t < 8; t++) {
                uint32_t bhi[2], blo[2];
                ldsm_x2(bhi, w_base + b_off + (t * 8 * APAD + ks) * 2);
                ldsm_x2(blo, wl_base + b_off + (t * 8 * APAD + ks) * 2);
                #pragma unroll
                for (int mt = 0; mt < 2; mt++) {
                    mma_bf16(acc[mt][t], ahi[mt], bhi);
                    mma_bf16(acc[mt][t], ahi[mt], blo);
                    mma_bf16(acc[mt][t], alo[mt], bhi);
                }
            }
        }
        __syncthreads();
    }

    // epilogue: bias + relu + store
    const int gq = lane >> 2, tq = lane & 3;
    #pragma unroll
    for (int mt = 0; mt < 2; mt++) {
        int m0 = bm + warp_m * 32 + mt * 16 + gq;
        #pragma unroll
        for (int t = 0; t < 8; t++) {
            int n = bn + warp_n * 64 + t * 8 + tq * 2;
            float bx = bias[n], by = bias[n + 1];
            if (m0 < N_NODES) {
                float2 o;
                o.x = fmaxf(acc[mt][t][0] + bx, 0.0f);
                o.y = fmaxf(acc[mt][t][1] + by, 0.0f);
                *(float2*)&g_hid[(size_t)m0 * NHID + n] = o;
            }
            if (m0 + 8 < N_NODES) {
                float2 o;
                o.x = fmaxf(acc[mt][t][2] + bx, 0.0f);
                o.y = fmaxf(acc[mt][t][3] + by, 0.0f);
                *(float2*)&g_hid[(size_t)(m0 + 8) * NHID + n] = o;
            }
        }
    }
}

// ---------------- GEMM2: h = hid @ W2 + b2; hA = h; out = gamma0*h ---------
__global__ void __launch_bounds__(256) k_gemm2(const float* __restrict__ W2,
                                               const float* __restrict__ b2,
                                               const float* __restrict__ gamma,
                                               float* __restrict__ out) {
    __shared__ float sW[NHID * NCLASS];  // 16 KB
    const int tid = threadIdx.x;
    for (int i = tid; i < NHID * NCLASS; i += 256) sW[i] = W2[i];
    __syncthreads();
    const int node = blockIdx.x * 16 + (tid >> 4);
    const int c = tid & 15;
    const float4* hr = (const float4*)(g_hid + (size_t)node * NHID);
    float acc = 0.0f;
    #pragma unroll 8
    for (int kk = 0; kk < NHID / 4; kk++) {
        float4 h4 = hr[kk];
        int k = kk * 4;
        acc += h4.x * sW[(k + 0) * NCLASS + c];
        acc += h4.y * sW[(k + 1) * NCLASS + c];
        acc += h4.z * sW[(k + 2) * NCLASS + c];
        acc += h4.w * sW[(k + 3) * NCLASS + c];
    }
    float v = acc + b2[c];
    g_hA[(size_t)node * NCLASS + c] = v;
    out[(size_t)node * NCLASS + c] = gamma[0] * v;
}

// ---------------- propagation: one warp per node, CSR gather, no atomics ---
__global__ void __launch_bounds__(256) k_prop(const float* __restrict__ gamma,
                                              float* __restrict__ out,
                                              int k, int flip) {
    const int gwarp = (blockIdx.x * blockDim.x + threadIdx.x) >> 5;
    if (gwarp >= N_NODES) return;
    const float* __restrict__ hin  = flip ? g_hB : g_hA;
    float* __restrict__       hout = flip ? g_hA : g_hB;
    const int lane = threadIdx.x & 31;
    const int c = lane & 15;
    const int half = lane >> 4;
    const int start = g_colptr[gwarp];
    const int len = g_cnt_col[gwarp];
    const int* __restrict__ rows = g_csr_row + start;

    float acc = 0.0f;
    int i = half;
    for (; i + 2 < len; i += 4) {
        int r0 = rows[i];
        int r1 = rows[i + 2];
        acc += g_s[r0] * hin[(size_t)r0 * NCLASS + c];
        acc += g_s[r1] * hin[(size_t)r1 * NCLASS + c];
    }
    if (i < len) {
        int r = rows[i];
        acc += g_s[r] * hin[(size_t)r * NCLASS + c];
    }
    acc += __shfl_down_sync(0xffffffffu, acc, 16);
    if (half == 0) {
        float hv = g_s[gwarp] * acc;
        hout[(size_t)gwarp * NCLASS + c] = hv;
        out[(size_t)gwarp * NCLASS + c] += gamma[k] * hv;
    }
}

// ---------------- launch ----------------------------------------------------
extern "C" void kernel_launch(void* const* d_in, const int* in_sizes, int n_in,
                              void* d_out, int out_size) {
    const float* x     = (const float*)d_in[0];
    const int*   ei    = (const int*)  d_in[1];
    const float* W1    = (const float*)d_in[2];
    const float* b1    = (const float*)d_in[3];
    const float* W2    = (const float*)d_in[4];
    const float* b2    = (const float*)d_in[5];
    const float* gamma = (const float*)d_in[6];
    float* out = (float*)d_out;

    // graph preprocessing
    k_init_counts<<<(N_NODES + 255) / 256, 256>>>();
    k_hist<<<(N_EDGES + 255) / 256, 256>>>(ei);
    k_compute_s<<<(N_NODES + 255) / 256, 256>>>();
    k_scan1<<<NBLK_SCAN, 1024>>>();
    k_scan2<<<1, 128>>>();
    k_scan3<<<(N_NODES + 255) / 256, 256>>>();
    k_csr_fill<<<(N_EDGES + 255) / 256, 256>>>(ei);

    // W1 split-bf16 prep + tensor-core GEMM1 (mma.sync path)
    k_wprep<<<(NHID * NFEAT + 255) / 256, 256>>>(W1);
    k_gemm1_mma<<<dim3(NHID / 128, (N_NODES + 127) / 128), 256>>>(x, b1);

    k_gemm2<<<N_NODES / 16, 256>>>(W2, b2, gamma, out);

    // K propagation steps (ping-pong hA/hB)
    const int prop_blocks = (N_NODES * 32 + 255) / 256;
    for (int k = 1; k <= KSTEPS; k++)
        k_prop<<<prop_blocks, 256>>>(gamma, out, k, (k - 1) & 1);
}

// round 7
// speedup vs baseline: 1.5813x; 1.0718x over previous
#include <cuda_runtime.h>
#include <cuda_bf16.h>
#include <stdint.h>

#define N_NODES 100000
#define N_EDGES 3200000
#define NFEAT   512
#define NHID    256
#define NCLASS  16
#define KSTEPS  10
#define NBLK_SCAN 98   // ceil(100000/1024)

// ---------------- scratch (device globals: no allocation allowed) ----------
__device__ float g_hid[(size_t)N_NODES * NHID];     // 102.4 MB
__device__ float g_hA[(size_t)N_NODES * NCLASS];    // 6.4 MB
__device__ float g_hB[(size_t)N_NODES * NCLASS];    // 6.4 MB
__device__ int   g_cnt_row[N_NODES];
__device__ int   g_cnt_col[N_NODES];
__device__ int   g_colptr[N_NODES];
__device__ int   g_fill[N_NODES];
__device__ float g_s[N_NODES];
__device__ int   g_csr_row[N_EDGES];                // 12.8 MB
__device__ int   g_bsum[NBLK_SCAN];
__device__ int   g_boff[NBLK_SCAN];
// W1 transposed + split to bf16 hi/lo: [NHID=256 rows][NFEAT=512 cols] K-major
__device__ uint4 g_W4hi[16384];                     // 256 KB
__device__ uint4 g_W4lo[16384];                     // 256 KB

// ---------------- graph preprocessing --------------------------------------
__global__ void k_init_counts() {
    int i = blockIdx.x * blockDim.x + threadIdx.x;
    if (i < N_NODES) { g_cnt_row[i] = 0; g_cnt_col[i] = 0; }
}

__global__ void k_hist(const int* __restrict__ ei) {
    int e = blockIdx.x * blockDim.x + threadIdx.x;
    if (e < N_EDGES) {
        atomicAdd(&g_cnt_row[ei[e]], 1);
        atomicAdd(&g_cnt_col[ei[N_EDGES + e]], 1);
    }
}

__global__ void k_compute_s() {
    int i = blockIdx.x * blockDim.x + threadIdx.x;
    if (i < N_NODES) {
        int d = g_cnt_row[i];
        g_s[i] = (d > 0) ? rsqrtf((float)d) : 0.0f;
    }
}

// parallel scan, stage 1: per-block exclusive scan + block sums
__global__ void __launch_bounds__(1024) k_scan1() {
    __shared__ int wsum[32];
    const int tid = threadIdx.x, lane = tid & 31, wid = tid >> 5;
    int i = blockIdx.x * 1024 + tid;
    int v = (i < N_NODES) ? g_cnt_col[i] : 0;
    int x = v;
    #pragma unroll
    for (int o = 1; o < 32; o <<= 1) {
        int y = __shfl_up_sync(0xffffffffu, x, o);
        if (lane >= o) x += y;
    }
    if (lane == 31) wsum[wid] = x;
    __syncthreads();
    if (wid == 0) {
        int w = wsum[lane];
        #pragma unroll
        for (int o = 1; o < 32; o <<= 1) {
            int y = __shfl_up_sync(0xffffffffu, w, o);
            if (lane >= o) w += y;
        }
        wsum[lane] = w;
    }
    __syncthreads();
    int excl = (wid ? wsum[wid - 1] : 0) + x - v;
    if (i < N_NODES) g_colptr[i] = excl;
    if (tid == 1023) g_bsum[blockIdx.x] = wsum[31];
}

// stage 2: scan the 98 block sums (single small block)
__global__ void k_scan2() {
    __shared__ int s[128];
    int tid = threadIdx.x;
    int v = (tid < NBLK_SCAN) ? g_bsum[tid] : 0;
    s[tid] = v;
    __syncthreads();
    for (int o = 1; o < 128; o <<= 1) {
        int t = (tid >= o) ? s[tid - o] : 0;
        __syncthreads();
        s[tid] += t;
        __syncthreads();
    }
    if (tid < NBLK_SCAN) g_boff[tid] = s[tid] - v;
}

// stage 3: add block offsets
__global__ void k_scan3() {
    int i = blockIdx.x * blockDim.x + threadIdx.x;
    if (i < N_NODES) {
        int v = g_colptr[i] + g_boff[i >> 10];
        g_colptr[i] = v;
        g_fill[i] = v;
    }
}

__global__ void k_csr_fill(const int* __restrict__ ei) {
    int e = blockIdx.x * blockDim.x + threadIdx.x;
    if (e < N_EDGES) {
        int r = ei[e];
        int c = ei[N_EDGES + e];
        int pos = atomicAdd(&g_fill[c], 1);
        g_csr_row[pos] = r;
    }
}

// ---------------- W1 prep: transpose + bf16 hi/lo split --------------------
__global__ void k_wprep(const float* __restrict__ W1) {
    int t = blockIdx.x * blockDim.x + threadIdx.x;
    if (t >= NHID * NFEAT) return;
    int n = t >> 9;        // 0..255
    int k = t & 511;       // 0..511
    float v = W1[(size_t)k * NHID + n];
    __nv_bfloat16 h = __float2bfloat16_rn(v);
    float lo = v - __bfloat162float(h);
    ((__nv_bfloat16*)g_W4hi)[(size_t)n * NFEAT + k] = h;
    ((__nv_bfloat16*)g_W4lo)[(size_t)n * NFEAT + k] = __float2bfloat16_rn(lo);
}

// ---------------- mma.sync helpers (sm_80+ baseline, works on sm_100) ------
__device__ __forceinline__ uint32_t smem_u32(const void* p) {
    uint32_t a;
    asm("{ .reg .u64 t; cvta.to.shared.u64 t, %1; cvt.u32.u64 %0, t; }" : "=r"(a) : "l"(p));
    return a;
}
__device__ __forceinline__ void ldsm_x4(uint32_t* r, uint32_t addr) {
    asm volatile("ldmatrix.sync.aligned.m8n8.x4.shared.b16 {%0,%1,%2,%3}, [%4];"
                 : "=r"(r[0]), "=r"(r[1]), "=r"(r[2]), "=r"(r[3]) : "r"(addr));
}
__device__ __forceinline__ void mma_bf16(float* c, const uint32_t* a, const uint32_t* b) {
    asm volatile("mma.sync.aligned.m16n8k16.row.col.f32.bf16.bf16.f32 "
                 "{%0,%1,%2,%3}, {%4,%5,%6,%7}, {%8,%9}, {%0,%1,%2,%3};"
                 : "+f"(c[0]), "+f"(c[1]), "+f"(c[2]), "+f"(c[3])
                 : "r"(a[0]), "r"(a[1]), "r"(a[2]), "r"(a[3]), "r"(b[0]), "r"(b[1]));
}

// ---- GEMM1: hid = relu(x@W1+b1), bf16x3 via mma.sync, BM=128 BN=128 BK=32 -
#define APAD 40   // row stride in bf16 elems (32 + 8 pad) -> 80B, LDSM conflict-free

__global__ void __launch_bounds__(256, 2) k_gemm1_mma(const float* __restrict__ A,
                                                      const float* __restrict__ bias) {
    __shared__ __align__(16) __nv_bfloat16 sAhi[128 * APAD];
    __shared__ __align__(16) __nv_bfloat16 sAlo[128 * APAD];
    __shared__ __align__(16) __nv_bfloat16 sWhi[128 * APAD];
    __shared__ __align__(16) __nv_bfloat16 sWlo[128 * APAD];

    const int tid = threadIdx.x;
    const int wid = tid >> 5, lane = tid & 31;
    const int warp_m = wid & 3;          // 4 warps in M, 32 rows each
    const int warp_n = wid >> 2;         // 2 warps in N, 64 cols each
    const int bm = blockIdx.y * 128;
    const int bn = blockIdx.x * 128;

    float acc[2][8][4];                  // [m16 tile][n8 tile][frag]
    #pragma unroll
    for (int mt = 0; mt < 2; mt++)
        #pragma unroll
        for (int t = 0; t < 8; t++)
            #pragma unroll
            for (int j = 0; j < 4; j++) acc[mt][t][j] = 0.0f;

    // precomputed ldmatrix smem addresses (byte offsets constant per thread)
    const int lr16 = lane & 15;
    const uint32_t a_base = smem_u32(sAhi);
    const uint32_t al_base = smem_u32(sAlo);
    const uint32_t w_base = smem_u32(sWhi);
    const uint32_t wl_base = smem_u32(sWlo);
    const uint32_t a_off = (uint32_t)(((warp_m * 32 + lr16) * APAD + (lane >> 4) * 8) * 2);
    // B x4: lanes 0-7: n tile t rows @ks, 8-15: @ks+8, 16-23: tile t+1 @ks, 24-31: @ks+8
    const uint32_t b4_off = (uint32_t)(((warp_n * 64 + (lane & 7) + ((lane >> 4) * 8)) * APAD
                                        + (((lane >> 3) & 1) * 8)) * 2);

    for (int k0 = 0; k0 < NFEAT; k0 += 32) {
        // stage A: 128 rows x 32 cols fp32 -> hi/lo bf16
        #pragma unroll
        for (int i = 0; i < 4; i++) {
            int u = i * 256 + tid;        // 0..1023
            int r = u >> 3, q = u & 7;    // row, float4 slot
            float4 v = make_float4(0.f, 0.f, 0.f, 0.f);
            if (bm + r < N_NODES)
                v = *(const float4*)(A + (size_t)(bm + r) * NFEAT + k0 + q * 4);
            __nv_bfloat16 h0 = __float2bfloat16_rn(v.x), h1 = __float2bfloat16_rn(v.y);
            __nv_bfloat16 h2 = __float2bfloat16_rn(v.z), h3 = __float2bfloat16_rn(v.w);
            uint2 ph, pl;
            ph.x = ((uint32_t)__bfloat16_as_ushort(h1) << 16) | __bfloat16_as_ushort(h0);
            ph.y = ((uint32_t)__bfloat16_as_ushort(h3) << 16) | __bfloat16_as_ushort(h2);
            __nv_bfloat16 l0 = __float2bfloat16_rn(v.x - __bfloat162float(h0));
            __nv_bfloat16 l1 = __float2bfloat16_rn(v.y - __bfloat162float(h1));
            __nv_bfloat16 l2 = __float2bfloat16_rn(v.z - __bfloat162float(h2));
            __nv_bfloat16 l3 = __float2bfloat16_rn(v.w - __bfloat162float(h3));
            pl.x = ((uint32_t)__bfloat16_as_ushort(l1) << 16) | __bfloat16_as_ushort(l0);
            pl.y = ((uint32_t)__bfloat16_as_ushort(l3) << 16) | __bfloat16_as_ushort(l2);
            *(uint2*)&sAhi[r * APAD + q * 4] = ph;
            *(uint2*)&sAlo[r * APAD + q * 4] = pl;
        }
        // stage W: 128 rows x 32 cols bf16 (hi/lo), from K-major g_W4
        #pragma unroll
        for (int i = 0; i < 2; i++) {
            int u = i * 256 + tid;        // 0..511
            int n = u >> 2, kk = u & 3;   // row, uint4 slot
            int gi = (bn + n) * 64 + (k0 >> 3) + kk;
            *(uint4*)&sWhi[n * APAD + kk * 8] = g_W4hi[gi];
            *(uint4*)&sWlo[n * APAD + kk * 8] = g_W4lo[gi];
        }
        __syncthreads();

        #pragma unroll
        for (int ks = 0; ks < 32; ks += 16) {
            uint32_t ahi[2][4], alo[2][4];
            ldsm_x4(ahi[0], a_base + a_off + ks * 2);
            ldsm_x4(ahi[1], a_base + a_off + (16 * APAD + ks) * 2);
            ldsm_x4(alo[0], al_base + a_off + ks * 2);
            ldsm_x4(alo[1], al_base + a_off + (16 * APAD + ks) * 2);
            #pragma unroll
            for (int t = 0; t < 8; t += 2) {
                uint32_t bhi[4], blo[4];   // [0,1]=tile t, [2,3]=tile t+1
                ldsm_x4(bhi, w_base + b4_off + (t * 8 * APAD + ks) * 2);
                ldsm_x4(blo, wl_base + b4_off + (t * 8 * APAD + ks) * 2);
                #pragma unroll
                for (int mt = 0; mt < 2; mt++) {
                    mma_bf16(acc[mt][t],     ahi[mt], bhi);
                    mma_bf16(acc[mt][t],     ahi[mt], blo);
                    mma_bf16(acc[mt][t],     alo[mt], bhi);
                    mma_bf16(acc[mt][t + 1], ahi[mt], bhi + 2);
                    mma_bf16(acc[mt][t + 1], ahi[mt], blo + 2);
                    mma_bf16(acc[mt][t + 1], alo[mt], bhi + 2);
                }
            }
        }
        __syncthreads();
    }

    // epilogue: bias + relu + store
    const int gq = lane >> 2, tq = lane & 3;
    #pragma unroll
    for (int mt = 0; mt < 2; mt++) {
        int m0 = bm + warp_m * 32 + mt * 16 + gq;
        #pragma unroll
        for (int t = 0; t < 8; t++) {
            int n = bn + warp_n * 64 + t * 8 + tq * 2;
            float bx = bias[n], by = bias[n + 1];
            if (m0 < N_NODES) {
                float2 o;
                o.x = fmaxf(acc[mt][t][0] + bx, 0.0f);
                o.y = fmaxf(acc[mt][t][1] + by, 0.0f);
                *(float2*)&g_hid[(size_t)m0 * NHID + n] = o;
            }
            if (m0 + 8 < N_NODES) {
                float2 o;
                o.x = fmaxf(acc[mt][t][2] + bx, 0.0f);
                o.y = fmaxf(acc[mt][t][3] + by, 0.0f);
                *(float2*)&g_hid[(size_t)(m0 + 8) * NHID + n] = o;
            }
        }
    }
}

// ---------------- GEMM2: h = hid @ W2 + b2; hA = h; out = gamma0*h ---------
__global__ void __launch_bounds__(256) k_gemm2(const float* __restrict__ W2,
                                               const float* __restrict__ b2,
                                               const float* __restrict__ gamma,
                                               float* __restrict__ out) {
    __shared__ float sW[NHID * NCLASS];  // 16 KB
    const int tid = threadIdx.x;
    for (int i = tid; i < NHID * NCLASS; i += 256) sW[i] = W2[i];
    __syncthreads();
    const int node = blockIdx.x * 16 + (tid >> 4);
    const int c = tid & 15;
    const float4* hr = (const float4*)(g_hid + (size_t)node * NHID);
    float acc = 0.0f;
    #pragma unroll 8
    for (int kk = 0; kk < NHID / 4; kk++) {
        float4 h4 = hr[kk];
        int k = kk * 4;
        acc += h4.x * sW[(k + 0) * NCLASS + c];
        acc += h4.y * sW[(k + 1) * NCLASS + c];
        acc += h4.z * sW[(k + 2) * NCLASS + c];
        acc += h4.w * sW[(k + 3) * NCLASS + c];
    }
    float v = acc + b2[c];
    g_hA[(size_t)node * NCLASS + c] = v;
    out[(size_t)node * NCLASS + c] = gamma[0] * v;
}

// ---- propagation: 1 warp/node, 4 lanes/edge (float4), 8 slots, no atomics -
// h_new[v] = s[v] * sum_{e: col(e)=v} s[row(e)] * h_in[row(e)];  out += g_k*h_new
__global__ void __launch_bounds__(256) k_prop(const float* __restrict__ gamma,
                                              float* __restrict__ out,
                                              int k, int flip) {
    const int gwarp = (blockIdx.x * blockDim.x + threadIdx.x) >> 5;
    if (gwarp >= N_NODES) return;
    const float4* __restrict__ hin  = (const float4*)(flip ? g_hB : g_hA);
    float4* __restrict__       hout = (float4*)(flip ? g_hA : g_hB);
    const int lane = threadIdx.x & 31;
    const int q = lane & 3;          // float4 slot within row (4 classes)
    const int slot = lane >> 2;      // edge slot 0..7
    const int start = g_colptr[gwarp];
    const int len = g_cnt_col[gwarp];
    const int* __restrict__ rows = g_csr_row + start;

    float4 acc = make_float4(0.f, 0.f, 0.f, 0.f);
    int i = slot;
    for (; i + 8 < len; i += 16) {   // 2 edges per slot-iter (16 across warp)
        int r0 = rows[i];
        int r1 = rows[i + 8];
        float s0 = g_s[r0], s1 = g_s[r1];
        float4 v0 = hin[r0 * 4 + q];
        float4 v1 = hin[r1 * 4 + q];
        acc.x += s0 * v0.x + s1 * v1.x;
        acc.y += s0 * v0.y + s1 * v1.y;
        acc.z += s0 * v0.z + s1 * v1.z;
        acc.w += s0 * v0.w + s1 * v1.w;
    }
    if (i < len) {
        int r = rows[i];
        float s = g_s[r];
        float4 v = hin[r * 4 + q];
        acc.x += s * v.x; acc.y += s * v.y; acc.z += s * v.z; acc.w += s * v.w;
    }
    // reduce across the 8 slots (lanes differing in bits 2..4)
    #pragma unroll
    for (int o = 4; o <= 16; o <<= 1) {
        acc.x += __shfl_xor_sync(0xffffffffu, acc.x, o);
        acc.y += __shfl_xor_sync(0xffffffffu, acc.y, o);
        acc.z += __shfl_xor_sync(0xffffffffu, acc.z, o);
        acc.w += __shfl_xor_sync(0xffffffffu, acc.w, o);
    }
    if (slot == 0) {
        float sv = g_s[gwarp];
        float4 hv = make_float4(sv * acc.x, sv * acc.y, sv * acc.z, sv * acc.w);
        hout[gwarp * 4 + q] = hv;
        float gk = gamma[k];
        float4* o4p = (float4*)out + gwarp * 4 + q;
        float4 o4 = *o4p;
        o4.x += gk * hv.x; o4.y += gk * hv.y; o4.z += gk * hv.z; o4.w += gk * hv.w;
        *o4p = o4;
    }
}

// ---------------- launch ----------------------------------------------------
// NOTE: launch order places k_gemm1_mma 4th — the profiler captures launch #4.
extern "C" void kernel_launch(void* const* d_in, const int* in_sizes, int n_in,
                              void* d_out, int out_size) {
    const float* x     = (const float*)d_in[0];
    const int*   ei    = (const int*)  d_in[1];
    const float* W1    = (const float*)d_in[2];
    const float* b1    = (const float*)d_in[3];
    const float* W2    = (const float*)d_in[4];
    const float* b2    = (const float*)d_in[5];
    const float* gamma = (const float*)d_in[6];
    float* out = (float*)d_out;

    // 1-3: prep that GEMM1 needs + independent graph work
    k_wprep<<<(NHID * NFEAT + 255) / 256, 256>>>(W1);
    k_init_counts<<<(N_NODES + 255) / 256, 256>>>();
    k_hist<<<(N_EDGES + 255) / 256, 256>>>(ei);
    // 4: the kernel we want ncu to capture
    k_gemm1_mma<<<dim3(NHID / 128, (N_NODES + 127) / 128), 256>>>(x, b1);
    // graph preprocessing (depends on hist)
    k_compute_s<<<(N_NODES + 255) / 256, 256>>>();
    k_scan1<<<NBLK_SCAN, 1024>>>();
    k_scan2<<<1, 128>>>();
    k_scan3<<<(N_NODES + 255) / 256, 256>>>();
    k_csr_fill<<<(N_EDGES + 255) / 256, 256>>>(ei);

    k_gemm2<<<N_NODES / 16, 256>>>(W2, b2, gamma, out);

    // K propagation steps (ping-pong hA/hB)
    const int prop_blocks = (N_NODES * 32 + 255) / 256;
    for (int k = 1; k <= KSTEPS; k++)
        k_prop<<<prop_blocks, 256>>>(gamma, out, k, (k - 1) & 1);
}

// round 8
// speedup vs baseline: 1.6004x; 1.0121x over previous
#include <cuda_runtime.h>
#include <cuda_bf16.h>
#include <stdint.h>

#define N_NODES 100000
#define N_EDGES 3200000
#define NFEAT   512
#define NHID    256
#define NCLASS  16
#define KSTEPS  10
#define NBLK_SCAN 98   // ceil(100000/1024)

// ---------------- scratch (device globals: no allocation allowed) ----------
__device__ float g_hid[(size_t)N_NODES * NHID];     // 102.4 MB
__device__ float g_hA[(size_t)N_NODES * NCLASS];    // 6.4 MB
__device__ float g_hB[(size_t)N_NODES * NCLASS];    // 6.4 MB
__device__ int   g_cnt_row[N_NODES];
__device__ int   g_cnt_col[N_NODES];
__device__ int   g_colptr[N_NODES];
__device__ int   g_fill[N_NODES];
__device__ float g_s[N_NODES];
__device__ int   g_csr_row[N_EDGES];                // 12.8 MB
__device__ int   g_bsum[NBLK_SCAN];
__device__ int   g_boff[NBLK_SCAN];
// W1 transposed + split to bf16 hi/lo: [NHID=256 rows][NFEAT=512 cols] K-major
__device__ uint4 g_W4hi[16384];                     // 256 KB
__device__ uint4 g_W4lo[16384];                     // 256 KB

// ---------------- graph preprocessing --------------------------------------
__global__ void k_init_counts() {
    int i = blockIdx.x * blockDim.x + threadIdx.x;
    if (i < N_NODES) { g_cnt_row[i] = 0; g_cnt_col[i] = 0; }
}

__global__ void k_hist(const int* __restrict__ ei) {
    int e = blockIdx.x * blockDim.x + threadIdx.x;
    if (e < N_EDGES) {
        atomicAdd(&g_cnt_row[ei[e]], 1);
        atomicAdd(&g_cnt_col[ei[N_EDGES + e]], 1);
    }
}

__global__ void k_compute_s() {
    int i = blockIdx.x * blockDim.x + threadIdx.x;
    if (i < N_NODES) {
        int d = g_cnt_row[i];
        g_s[i] = (d > 0) ? rsqrtf((float)d) : 0.0f;
    }
}

// parallel scan, stage 1: per-block exclusive scan + block sums
__global__ void __launch_bounds__(1024) k_scan1() {
    __shared__ int wsum[32];
    const int tid = threadIdx.x, lane = tid & 31, wid = tid >> 5;
    int i = blockIdx.x * 1024 + tid;
    int v = (i < N_NODES) ? g_cnt_col[i] : 0;
    int x = v;
    #pragma unroll
    for (int o = 1; o < 32; o <<= 1) {
        int y = __shfl_up_sync(0xffffffffu, x, o);
        if (lane >= o) x += y;
    }
    if (lane == 31) wsum[wid] = x;
    __syncthreads();
    if (wid == 0) {
        int w = wsum[lane];
        #pragma unroll
        for (int o = 1; o < 32; o <<= 1) {
            int y = __shfl_up_sync(0xffffffffu, w, o);
            if (lane >= o) w += y;
        }
        wsum[lane] = w;
    }
    __syncthreads();
    int excl = (wid ? wsum[wid - 1] : 0) + x - v;
    if (i < N_NODES) g_colptr[i] = excl;
    if (tid == 1023) g_bsum[blockIdx.x] = wsum[31];
}

// stage 2: scan the 98 block sums (single small block)
__global__ void k_scan2() {
    __shared__ int s[128];
    int tid = threadIdx.x;
    int v = (tid < NBLK_SCAN) ? g_bsum[tid] : 0;
    s[tid] = v;
    __syncthreads();
    for (int o = 1; o < 128; o <<= 1) {
        int t = (tid >= o) ? s[tid - o] : 0;
        __syncthreads();
        s[tid] += t;
        __syncthreads();
    }
    if (tid < NBLK_SCAN) g_boff[tid] = s[tid] - v;
}

// stage 3: add block offsets
__global__ void k_scan3() {
    int i = blockIdx.x * blockDim.x + threadIdx.x;
    if (i < N_NODES) {
        int v = g_colptr[i] + g_boff[i >> 10];
        g_colptr[i] = v;
        g_fill[i] = v;
    }
}

__global__ void k_csr_fill(const int* __restrict__ ei) {
    int e = blockIdx.x * blockDim.x + threadIdx.x;
    if (e < N_EDGES) {
        int r = ei[e];
        int c = ei[N_EDGES + e];
        int pos = atomicAdd(&g_fill[c], 1);
        g_csr_row[pos] = r;
    }
}

// ---------------- W1 prep: transpose + bf16 hi/lo split --------------------
__global__ void k_wprep(const float* __restrict__ W1) {
    int t = blockIdx.x * blockDim.x + threadIdx.x;
    if (t >= NHID * NFEAT) return;
    int n = t >> 9;        // 0..255
    int k = t & 511;       // 0..511
    float v = W1[(size_t)k * NHID + n];
    __nv_bfloat16 h = __float2bfloat16_rn(v);
    float lo = v - __bfloat162float(h);
    ((__nv_bfloat16*)g_W4hi)[(size_t)n * NFEAT + k] = h;
    ((__nv_bfloat16*)g_W4lo)[(size_t)n * NFEAT + k] = __float2bfloat16_rn(lo);
}

// ---------------- mma.sync / cp.async helpers ------------------------------
__device__ __forceinline__ uint32_t smem_u32(const void* p) {
    uint32_t a;
    asm("{ .reg .u64 t; cvta.to.shared.u64 t, %1; cvt.u32.u64 %0, t; }" : "=r"(a) : "l"(p));
    return a;
}
__device__ __forceinline__ void ldsm_x4(uint32_t* r, uint32_t addr) {
    asm volatile("ldmatrix.sync.aligned.m8n8.x4.shared.b16 {%0,%1,%2,%3}, [%4];"
                 : "=r"(r[0]), "=r"(r[1]), "=r"(r[2]), "=r"(r[3]) : "r"(addr));
}
__device__ __forceinline__ void mma_bf16(float* c, const uint32_t* a, const uint32_t* b) {
    asm volatile("mma.sync.aligned.m16n8k16.row.col.f32.bf16.bf16.f32 "
                 "{%0,%1,%2,%3}, {%4,%5,%6,%7}, {%8,%9}, {%0,%1,%2,%3};"
                 : "+f"(c[0]), "+f"(c[1]), "+f"(c[2]), "+f"(c[3])
                 : "r"(a[0]), "r"(a[1]), "r"(a[2]), "r"(a[3]), "r"(b[0]), "r"(b[1]));
}
__device__ __forceinline__ void cp16(uint32_t saddr, const void* g) {
    asm volatile("cp.async.cg.shared.global [%0], [%1], 16;" :: "r"(saddr), "l"(g));
}
#define CP_COMMIT() asm volatile("cp.async.commit_group;" ::: "memory")
#define CP_WAIT0()  asm volatile("cp.async.wait_group 0;" ::: "memory")

// ---- GEMM1: hid = relu(x@W1+b1), bf16x3 mma.sync, double-buffered ---------
#define APAD 40               // row stride in bf16 elems -> 80B, LDSM conflict-free
#define TSZ  (128 * APAD)     // one tile array in bf16 elems (5120)
#define SM1_BYTES (2 * 4 * TSZ * 2)   // 2 buffers x 4 arrays x 5120 x 2B = 81920

__global__ void __launch_bounds__(256, 2) k_gemm1_mma(const float* __restrict__ A,
                                                      const float* __restrict__ bias) {
    extern __shared__ __align__(16) __nv_bfloat16 dyn[];
    // buffer b: [sAhi, sAlo, sWhi, sWlo] each TSZ elems
    __nv_bfloat16* base[2] = { dyn, dyn + 4 * TSZ };

    const int tid = threadIdx.x;
    const int wid = tid >> 5, lane = tid & 31;
    const int warp_m = wid & 3;          // 4 warps in M, 32 rows each
    const int warp_n = wid >> 2;         // 2 warps in N, 64 cols each
    const int bm = blockIdx.y * 128;
    const int bn = blockIdx.x * 128;

    float acc[2][8][4];
    #pragma unroll
    for (int mt = 0; mt < 2; mt++)
        #pragma unroll
        for (int t = 0; t < 8; t++)
            #pragma unroll
            for (int j = 0; j < 4; j++) acc[mt][t][j] = 0.0f;

    // per-thread staging indices
    const int ar = tid >> 1;                  // not used; staging via u below
    (void)ar;
    // ldmatrix offsets (relative to each array base)
    const int lr16 = lane & 15;
    const uint32_t a_off = (uint32_t)(((warp_m * 32 + lr16) * APAD + (lane >> 4) * 8) * 2);
    const uint32_t b4_off = (uint32_t)(((warp_n * 64 + (lane & 7) + ((lane >> 4) * 8)) * APAD
                                        + (((lane >> 3) & 1) * 8)) * 2);
    uint32_t ahi_b[2], alo_b[2], whi_b[2], wlo_b[2];
    #pragma unroll
    for (int b = 0; b < 2; b++) {
        ahi_b[b] = smem_u32(base[b]);
        alo_b[b] = smem_u32(base[b] + TSZ);
        whi_b[b] = smem_u32(base[b] + 2 * TSZ);
        wlo_b[b] = smem_u32(base[b] + 3 * TSZ);
    }

    // ---- staging helpers (inline lambdas) ----
    auto stageW = [&](int k0, int b) {
        #pragma unroll
        for (int i = 0; i < 2; i++) {
            int u = i * 256 + tid;            // 0..511
            int n = u >> 2, kk = u & 3;
            int gi = (bn + n) * 64 + (k0 >> 3) + kk;
            uint32_t off = (uint32_t)((n * APAD + kk * 8) * 2);
            cp16(whi_b[b] + off, &g_W4hi[gi]);
            cp16(wlo_b[b] + off, &g_W4lo[gi]);
        }
    };
    auto loadA = [&](int k0, float4* av) {
        #pragma unroll
        for (int i = 0; i < 4; i++) {
            int u = i * 256 + tid;            // 0..1023
            int r = u >> 3, q = u & 7;
            av[i] = make_float4(0.f, 0.f, 0.f, 0.f);
            if (bm + r < N_NODES)
                av[i] = *(const float4*)(A + (size_t)(bm + r) * NFEAT + k0 + q * 4);
        }
    };
    auto storeA = [&](const float4* av, int b) {
        __nv_bfloat16* sAhi = base[b];
        __nv_bfloat16* sAlo = base[b] + TSZ;
        #pragma unroll
        for (int i = 0; i < 4; i++) {
            int u = i * 256 + tid;
            int r = u >> 3, q = u & 7;
            float4 v = av[i];
            __nv_bfloat16 h0 = __float2bfloat16_rn(v.x), h1 = __float2bfloat16_rn(v.y);
            __nv_bfloat16 h2 = __float2bfloat16_rn(v.z), h3 = __float2bfloat16_rn(v.w);
            uint2 ph, pl;
            ph.x = ((uint32_t)__bfloat16_as_ushort(h1) << 16) | __bfloat16_as_ushort(h0);
            ph.y = ((uint32_t)__bfloat16_as_ushort(h3) << 16) | __bfloat16_as_ushort(h2);
            __nv_bfloat16 l0 = __float2bfloat16_rn(v.x - __bfloat162float(h0));
            __nv_bfloat16 l1 = __float2bfloat16_rn(v.y - __bfloat162float(h1));
            __nv_bfloat16 l2 = __float2bfloat16_rn(v.z - __bfloat162float(h2));
            __nv_bfloat16 l3 = __float2bfloat16_rn(v.w - __bfloat162float(h3));
            pl.x = ((uint32_t)__bfloat16_as_ushort(l1) << 16) | __bfloat16_as_ushort(l0);
            pl.y = ((uint32_t)__bfloat16_as_ushort(l3) << 16) | __bfloat16_as_ushort(l2);
            *(uint2*)&sAhi[r * APAD + q * 4] = ph;
            *(uint2*)&sAlo[r * APAD + q * 4] = pl;
        }
    };

    // ---- prologue: fill buffer 0 ----
    float4 av[4];
    stageW(0, 0);
    CP_COMMIT();
    loadA(0, av);
    storeA(av, 0);
    CP_WAIT0();
    __syncthreads();

    // ---- main loop: compute buf, prefetch nxt ----
    for (int k0 = 0; k0 < NFEAT; k0 += 32) {
        const int buf = (k0 >> 5) & 1;
        const int nxt = buf ^ 1;
        const bool hn = (k0 + 32) < NFEAT;
        if (hn) {
            stageW(k0 + 32, nxt);
            CP_COMMIT();
            loadA(k0 + 32, av);
        }
        // compute on buf
        #pragma unroll
        for (int ks = 0; ks < 32; ks += 16) {
            uint32_t ahi[2][4], alo[2][4];
            ldsm_x4(ahi[0], ahi_b[buf] + a_off + ks * 2);
            ldsm_x4(ahi[1], ahi_b[buf] + a_off + (16 * APAD + ks) * 2);
            ldsm_x4(alo[0], alo_b[buf] + a_off + ks * 2);
            ldsm_x4(alo[1], alo_b[buf] + a_off + (16 * APAD + ks) * 2);
            #pragma unroll
            for (int t = 0; t < 8; t += 2) {
                uint32_t bhi[4], blo[4];
                ldsm_x4(bhi, whi_b[buf] + b4_off + (t * 8 * APAD + ks) * 2);
                ldsm_x4(blo, wlo_b[buf] + b4_off + (t * 8 * APAD + ks) * 2);
                #pragma unroll
                for (int mt = 0; mt < 2; mt++) {
                    mma_bf16(acc[mt][t],     ahi[mt], bhi);
                    mma_bf16(acc[mt][t],     ahi[mt], blo);
                    mma_bf16(acc[mt][t],     alo[mt], bhi);
                    mma_bf16(acc[mt][t + 1], ahi[mt], bhi + 2);
                    mma_bf16(acc[mt][t + 1], ahi[mt], blo + 2);
                    mma_bf16(acc[mt][t + 1], alo[mt], bhi + 2);
                }
            }
        }
        if (hn) {
            storeA(av, nxt);
            CP_WAIT0();
        }
        __syncthreads();
    }

    // epilogue: bias + relu + store
    const int gq = lane >> 2, tq = lane & 3;
    #pragma unroll
    for (int mt = 0; mt < 2; mt++) {
        int m0 = bm + warp_m * 32 + mt * 16 + gq;
        #pragma unroll
        for (int t = 0; t < 8; t++) {
            int n = bn + warp_n * 64 + t * 8 + tq * 2;
            float bx = bias[n], by = bias[n + 1];
            if (m0 < N_NODES) {
                float2 o;
                o.x = fmaxf(acc[mt][t][0] + bx, 0.0f);
                o.y = fmaxf(acc[mt][t][1] + by, 0.0f);
                *(float2*)&g_hid[(size_t)m0 * NHID + n] = o;
            }
            if (m0 + 8 < N_NODES) {
                float2 o;
                o.x = fmaxf(acc[mt][t][2] + bx, 0.0f);
                o.y = fmaxf(acc[mt][t][3] + by, 0.0f);
                *(float2*)&g_hid[(size_t)(m0 + 8) * NHID + n] = o;
            }
        }
    }
}

// ---------------- GEMM2: h = hid @ W2 + b2; hA = h; out = gamma0*h ---------
__global__ void __launch_bounds__(256) k_gemm2(const float* __restrict__ W2,
                                               const float* __restrict__ b2,
                                               const float* __restrict__ gamma,
                                               float* __restrict__ out) {
    __shared__ float sW[NHID * NCLASS];  // 16 KB
    const int tid = threadIdx.x;
    for (int i = tid; i < NHID * NCLASS; i += 256) sW[i] = W2[i];
    __syncthreads();
    const int node = blockIdx.x * 16 + (tid >> 4);
    const int c = tid & 15;
    const float4* hr = (const float4*)(g_hid + (size_t)node * NHID);
    float acc = 0.0f;
    #pragma unroll 8
    for (int kk = 0; kk < NHID / 4; kk++) {
        float4 h4 = hr[kk];
        int k = kk * 4;
        acc += h4.x * sW[(k + 0) * NCLASS + c];
        acc += h4.y * sW[(k + 1) * NCLASS + c];
        acc += h4.z * sW[(k + 2) * NCLASS + c];
        acc += h4.w * sW[(k + 3) * NCLASS + c];
    }
    float v = acc + b2[c];
    g_hA[(size_t)node * NCLASS + c] = v;
    out[(size_t)node * NCLASS + c] = gamma[0] * v;
}

// ---- propagation: 1 warp/node, 4 lanes/edge (float4), 8 slots, no atomics -
__global__ void __launch_bounds__(256) k_prop(const float* __restrict__ gamma,
                                              float* __restrict__ out,
                                              int k, int flip) {
    const int gwarp = (blockIdx.x * blockDim.x + threadIdx.x) >> 5;
    if (gwarp >= N_NODES) return;
    const float4* __restrict__ hin  = (const float4*)(flip ? g_hB : g_hA);
    float4* __restrict__       hout = (float4*)(flip ? g_hA : g_hB);
    const int lane = threadIdx.x & 31;
    const int q = lane & 3;
    const int slot = lane >> 2;
    const int start = g_colptr[gwarp];
    const int len = g_cnt_col[gwarp];
    const int* __restrict__ rows = g_csr_row + start;

    float4 acc = make_float4(0.f, 0.f, 0.f, 0.f);
    int i = slot;
    for (; i + 8 < len; i += 16) {
        int r0 = rows[i];
        int r1 = rows[i + 8];
        float s0 = g_s[r0], s1 = g_s[r1];
        float4 v0 = hin[r0 * 4 + q];
        float4 v1 = hin[r1 * 4 + q];
        acc.x += s0 * v0.x + s1 * v1.x;
        acc.y += s0 * v0.y + s1 * v1.y;
        acc.z += s0 * v0.z + s1 * v1.z;
        acc.w += s0 * v0.w + s1 * v1.w;
    }
    if (i < len) {
        int r = rows[i];
        float s = g_s[r];
        float4 v = hin[r * 4 + q];
        acc.x += s * v.x; acc.y += s * v.y; acc.z += s * v.z; acc.w += s * v.w;
    }
    #pragma unroll
    for (int o = 4; o <= 16; o <<= 1) {
        acc.x += __shfl_xor_sync(0xffffffffu, acc.x, o);
        acc.y += __shfl_xor_sync(0xffffffffu, acc.y, o);
        acc.z += __shfl_xor_sync(0xffffffffu, acc.z, o);
        acc.w += __shfl_xor_sync(0xffffffffu, acc.w, o);
    }
    if (slot == 0) {
        float sv = g_s[gwarp];
        float4 hv = make_float4(sv * acc.x, sv * acc.y, sv * acc.z, sv * acc.w);
        hout[gwarp * 4 + q] = hv;
        float gk = gamma[k];
        float4* o4p = (float4*)out + gwarp * 4 + q;
        float4 o4 = *o4p;
        o4.x += gk * hv.x; o4.y += gk * hv.y; o4.z += gk * hv.z; o4.w += gk * hv.w;
        *o4p = o4;
    }
}

// ---------------- launch ----------------------------------------------------
// NOTE: launch order places k_gemm1_mma 4th — the profiler captures launch #4.
extern "C" void kernel_launch(void* const* d_in, const int* in_sizes, int n_in,
                              void* d_out, int out_size) {
    const float* x     = (const float*)d_in[0];
    const int*   ei    = (const int*)  d_in[1];
    const float* W1    = (const float*)d_in[2];
    const float* b1    = (const float*)d_in[3];
    const float* W2    = (const float*)d_in[4];
    const float* b2    = (const float*)d_in[5];
    const float* gamma = (const float*)d_in[6];
    float* out = (float*)d_out;

    static bool attr_set = false;
    if (!attr_set) {
        cudaFuncSetAttribute(k_gemm1_mma, cudaFuncAttributeMaxDynamicSharedMemorySize,
                             SM1_BYTES);
        attr_set = true;
    }

    // 1-3: prep that GEMM1 needs + independent graph work
    k_wprep<<<(NHID * NFEAT + 255) / 256, 256>>>(W1);
    k_init_counts<<<(N_NODES + 255) / 256, 256>>>();
    k_hist<<<(N_EDGES + 255) / 256, 256>>>(ei);
    // 4: the kernel we want ncu to capture
    k_gemm1_mma<<<dim3(NHID / 128, (N_NODES + 127) / 128), 256, SM1_BYTES>>>(x, b1);
    // graph preprocessing (depends on hist)
    k_compute_s<<<(N_NODES + 255) / 256, 256>>>();
    k_scan1<<<NBLK_SCAN, 1024>>>();
    k_scan2<<<1, 128>>>();
    k_scan3<<<(N_NODES + 255) / 256, 256>>>();
    k_csr_fill<<<(N_EDGES + 255) / 256, 256>>>(ei);

    k_gemm2<<<N_NODES / 16, 256>>>(W2, b2, gamma, out);

    // K propagation steps (ping-pong hA/hB)
    const int prop_blocks = (N_NODES * 32 + 255) / 256;
    for (int k = 1; k <= KSTEPS; k++)
        k_prop<<<prop_blocks, 256>>>(gamma, out, k, (k - 1) & 1);
}

// round 10
// speedup vs baseline: 1.7074x; 1.0668x over previous
#include <cuda_runtime.h>
#include <cuda_bf16.h>
#include <stdint.h>

#define N_NODES 100000
#define N_EDGES 3200000
#define NFEAT   512
#define NHID    256
#define NCLASS  16
#define KSTEPS  10
#define NBLK_SCAN 98   // ceil(100000/1024)

// ---------------- scratch (device globals: no allocation allowed) ----------
__device__ float g_hid[(size_t)N_NODES * NHID];     // 102.4 MB
__device__ float g_hA[(size_t)N_NODES * NCLASS];    // u ping
__device__ float g_hB[(size_t)N_NODES * NCLASS];    // u pong
__device__ float g_gacc[(size_t)N_NODES * NCLASS];  // sum_k gamma_k * u_k
__device__ int   g_cnt_row[N_NODES];
__device__ int   g_cnt_col[N_NODES];
__device__ int   g_colptr[N_NODES];
__device__ int   g_fill[N_NODES];
__device__ float g_s[N_NODES];
__device__ float g_sinv[N_NODES];                   // sqrt(deg) = 1/s (0 if deg=0)
__device__ int   g_csr_row[N_EDGES];                // 12.8 MB
__device__ int   g_bsum[NBLK_SCAN];
__device__ int   g_boff[NBLK_SCAN];
// W1 transposed + split to bf16 hi/lo: [NHID=256 rows][NFEAT=512 cols] K-major
__device__ uint4 g_W4hi[16384];                     // 256 KB
__device__ uint4 g_W4lo[16384];                     // 256 KB

// ---------------- graph preprocessing --------------------------------------
__global__ void k_init_counts() {
    int i = blockIdx.x * blockDim.x + threadIdx.x;
    if (i < N_NODES) { g_cnt_row[i] = 0; g_cnt_col[i] = 0; }
}

__global__ void k_hist(const int* __restrict__ ei) {
    int e = blockIdx.x * blockDim.x + threadIdx.x;
    if (e < N_EDGES) {
        atomicAdd(&g_cnt_row[ei[e]], 1);
        atomicAdd(&g_cnt_col[ei[N_EDGES + e]], 1);
    }
}

__global__ void k_compute_s() {
    int i = blockIdx.x * blockDim.x + threadIdx.x;
    if (i < N_NODES) {
        int d = g_cnt_row[i];
        g_s[i]    = (d > 0) ? rsqrtf((float)d) : 0.0f;
        g_sinv[i] = (d > 0) ? sqrtf((float)d)  : 0.0f;
    }
}

// parallel scan, stage 1: per-block exclusive scan + block sums
__global__ void __launch_bounds__(1024) k_scan1() {
    __shared__ int wsum[32];
    const int tid = threadIdx.x, lane = tid & 31, wid = tid >> 5;
    int i = blockIdx.x * 1024 + tid;
    int v = (i < N_NODES) ? g_cnt_col[i] : 0;
    int x = v;
    #pragma unroll
    for (int o = 1; o < 32; o <<= 1) {
        int y = __shfl_up_sync(0xffffffffu, x, o);
        if (lane >= o) x += y;
    }
    if (lane == 31) wsum[wid] = x;
    __syncthreads();
    if (wid == 0) {
        int w = wsum[lane];
        #pragma unroll
        for (int o = 1; o < 32; o <<= 1) {
            int y = __shfl_up_sync(0xffffffffu, w, o);
            if (lane >= o) w += y;
        }
        wsum[lane] = w;
    }
    __syncthreads();
    int excl = (wid ? wsum[wid - 1] : 0) + x - v;
    if (i < N_NODES) g_colptr[i] = excl;
    if (tid == 1023) g_bsum[blockIdx.x] = wsum[31];
}

// stage 2: scan the 98 block sums (single small block)
__global__ void k_scan2() {
    __shared__ int s[128];
    int tid = threadIdx.x;
    int v = (tid < NBLK_SCAN) ? g_bsum[tid] : 0;
    s[tid] = v;
    __syncthreads();
    for (int o = 1; o < 128; o <<= 1) {
        int t = (tid >= o) ? s[tid - o] : 0;
        __syncthreads();
        s[tid] += t;
        __syncthreads();
    }
    if (tid < NBLK_SCAN) g_boff[tid] = s[tid] - v;
}

// stage 3: add block offsets
__global__ void k_scan3() {
    int i = blockIdx.x * blockDim.x + threadIdx.x;
    if (i < N_NODES) {
        int v = g_colptr[i] + g_boff[i >> 10];
        g_colptr[i] = v;
        g_fill[i] = v;
    }
}

__global__ void k_csr_fill(const int* __restrict__ ei) {
    int e = blockIdx.x * blockDim.x + threadIdx.x;
    if (e < N_EDGES) {
        int r = ei[e];
        int c = ei[N_EDGES + e];
        int pos = atomicAdd(&g_fill[c], 1);
        g_csr_row[pos] = r;
    }
}

// ---------------- W1 prep: transpose + bf16 hi/lo split --------------------
__global__ void k_wprep(const float* __restrict__ W1) {
    int t = blockIdx.x * blockDim.x + threadIdx.x;
    if (t >= NHID * NFEAT) return;
    int n = t >> 9;        // 0..255
    int k = t & 511;       // 0..511
    float v = W1[(size_t)k * NHID + n];
    __nv_bfloat16 h = __float2bfloat16_rn(v);
    float lo = v - __bfloat162float(h);
    ((__nv_bfloat16*)g_W4hi)[(size_t)n * NFEAT + k] = h;
    ((__nv_bfloat16*)g_W4lo)[(size_t)n * NFEAT + k] = __float2bfloat16_rn(lo);
}

// ---------------- mma.sync / cp.async helpers ------------------------------
__device__ __forceinline__ uint32_t smem_u32(const void* p) {
    uint32_t a;
    asm("{ .reg .u64 t; cvta.to.shared.u64 t, %1; cvt.u32.u64 %0, t; }" : "=r"(a) : "l"(p));
    return a;
}
__device__ __forceinline__ void ldsm_x4(uint32_t* r, uint32_t addr) {
    asm volatile("ldmatrix.sync.aligned.m8n8.x4.shared.b16 {%0,%1,%2,%3}, [%4];"
                 : "=r"(r[0]), "=r"(r[1]), "=r"(r[2]), "=r"(r[3]) : "r"(addr));
}
__device__ __forceinline__ void mma_bf16(float* c, const uint32_t* a, const uint32_t* b) {
    asm volatile("mma.sync.aligned.m16n8k16.row.col.f32.bf16.bf16.f32 "
                 "{%0,%1,%2,%3}, {%4,%5,%6,%7}, {%8,%9}, {%0,%1,%2,%3};"
                 : "+f"(c[0]), "+f"(c[1]), "+f"(c[2]), "+f"(c[3])
                 : "r"(a[0]), "r"(a[1]), "r"(a[2]), "r"(a[3]), "r"(b[0]), "r"(b[1]));
}
__device__ __forceinline__ void cp16(uint32_t saddr, const void* g) {
    asm volatile("cp.async.cg.shared.global [%0], [%1], 16;" :: "r"(saddr), "l"(g));
}
#define CP_COMMIT() asm volatile("cp.async.commit_group;" ::: "memory")
#define CP_WAIT0()  asm volatile("cp.async.wait_group 0;" ::: "memory")

// ---- GEMM1: hid = relu(x@W1+b1), bf16x3 mma.sync, double-buffered ---------
#define APAD 40               // row stride in bf16 elems -> 80B, LDSM conflict-free
#define TSZ  (128 * APAD)     // one tile array in bf16 elems (5120)
#define SM1_BYTES (2 * 4 * TSZ * 2)   // 2 buffers x 4 arrays x 5120 x 2B = 81920

__global__ void __launch_bounds__(256, 2) k_gemm1_mma(const float* __restrict__ A,
                                                      const float* __restrict__ bias) {
    extern __shared__ __align__(16) __nv_bfloat16 dyn[];
    __nv_bfloat16* base[2] = { dyn, dyn + 4 * TSZ };

    const int tid = threadIdx.x;
    const int wid = tid >> 5, lane = tid & 31;
    const int warp_m = wid & 3;          // 4 warps in M, 32 rows each
    const int warp_n = wid >> 2;         // 2 warps in N, 64 cols each
    const int bm = blockIdx.y * 128;
    const int bn = blockIdx.x * 128;

    float acc[2][8][4];
    #pragma unroll
    for (int mt = 0; mt < 2; mt++)
        #pragma unroll
        for (int t = 0; t < 8; t++)
            #pragma unroll
            for (int j = 0; j < 4; j++) acc[mt][t][j] = 0.0f;

    const int lr16 = lane & 15;
    const uint32_t a_off = (uint32_t)(((warp_m * 32 + lr16) * APAD + (lane >> 4) * 8) * 2);
    const uint32_t b4_off = (uint32_t)(((warp_n * 64 + (lane & 7) + ((lane >> 4) * 8)) * APAD
                                        + (((lane >> 3) & 1) * 8)) * 2);
    uint32_t ahi_b[2], alo_b[2], whi_b[2], wlo_b[2];
    #pragma unroll
    for (int b = 0; b < 2; b++) {
        ahi_b[b] = smem_u32(base[b]);
        alo_b[b] = smem_u32(base[b] + TSZ);
        whi_b[b] = smem_u32(base[b] + 2 * TSZ);
        wlo_b[b] = smem_u32(base[b] + 3 * TSZ);
    }

    auto stageW = [&](int k0, int b) {
        #pragma unroll
        for (int i = 0; i < 2; i++) {
            int u = i * 256 + tid;
            int n = u >> 2, kk = u & 3;
            int gi = (bn + n) * 64 + (k0 >> 3) + kk;
            uint32_t off = (uint32_t)((n * APAD + kk * 8) * 2);
            cp16(whi_b[b] + off, &g_W4hi[gi]);
            cp16(wlo_b[b] + off, &g_W4lo[gi]);
        }
    };
    auto loadA = [&](int k0, float4* av) {
        #pragma unroll
        for (int i = 0; i < 4; i++) {
            int u = i * 256 + tid;
            int r = u >> 3, q = u & 7;
            av[i] = make_float4(0.f, 0.f, 0.f, 0.f);
            if (bm + r < N_NODES)
                av[i] = *(const float4*)(A + (size_t)(bm + r) * NFEAT + k0 + q * 4);
        }
    };
    auto storeA = [&](const float4* av, int b) {
        __nv_bfloat16* sAhi = base[b];
        __nv_bfloat16* sAlo = base[b] + TSZ;
        #pragma unroll
        for (int i = 0; i < 4; i++) {
            int u = i * 256 + tid;
            int r = u >> 3, q = u & 7;
            float4 v = av[i];
            __nv_bfloat16 h0 = __float2bfloat16_rn(v.x), h1 = __float2bfloat16_rn(v.y);
            __nv_bfloat16 h2 = __float2bfloat16_rn(v.z), h3 = __float2bfloat16_rn(v.w);
            uint2 ph, pl;
            ph.x = ((uint32_t)__bfloat16_as_ushort(h1) << 16) | __bfloat16_as_ushort(h0);
            ph.y = ((uint32_t)__bfloat16_as_ushort(h3) << 16) | __bfloat16_as_ushort(h2);
            __nv_bfloat16 l0 = __float2bfloat16_rn(v.x - __bfloat162float(h0));
            __nv_bfloat16 l1 = __float2bfloat16_rn(v.y - __bfloat162float(h1));
            __nv_bfloat16 l2 = __float2bfloat16_rn(v.z - __bfloat162float(h2));
            __nv_bfloat16 l3 = __float2bfloat16_rn(v.w - __bfloat162float(h3));
            pl.x = ((uint32_t)__bfloat16_as_ushort(l1) << 16) | __bfloat16_as_ushort(l0);
            pl.y = ((uint32_t)__bfloat16_as_ushort(l3) << 16) | __bfloat16_as_ushort(l2);
            *(uint2*)&sAhi[r * APAD + q * 4] = ph;
            *(uint2*)&sAlo[r * APAD + q * 4] = pl;
        }
    };

    float4 av[4];
    stageW(0, 0);
    CP_COMMIT();
    loadA(0, av);
    storeA(av, 0);
    CP_WAIT0();
    __syncthreads();

    for (int k0 = 0; k0 < NFEAT; k0 += 32) {
        const int buf = (k0 >> 5) & 1;
        const int nxt = buf ^ 1;
        const bool hn = (k0 + 32) < NFEAT;
        if (hn) {
            stageW(k0 + 32, nxt);
            CP_COMMIT();
            loadA(k0 + 32, av);
        }
        #pragma unroll
        for (int ks = 0; ks < 32; ks += 16) {
            uint32_t ahi[2][4], alo[2][4];
            ldsm_x4(ahi[0], ahi_b[buf] + a_off + ks * 2);
            ldsm_x4(ahi[1], ahi_b[buf] + a_off + (16 * APAD + ks) * 2);
            ldsm_x4(alo[0], alo_b[buf] + a_off + ks * 2);
            ldsm_x4(alo[1], alo_b[buf] + a_off + (16 * APAD + ks) * 2);
            #pragma unroll
            for (int t = 0; t < 8; t += 2) {
                uint32_t bhi[4], blo[4];
                ldsm_x4(bhi, whi_b[buf] + b4_off + (t * 8 * APAD + ks) * 2);
                ldsm_x4(blo, wlo_b[buf] + b4_off + (t * 8 * APAD + ks) * 2);
                // RAW distance 4: each acc updated 3x, separated by 3 other accs
                mma_bf16(acc[0][t],     ahi[0], bhi);
                mma_bf16(acc[0][t + 1], ahi[0], bhi + 2);
                mma_bf16(acc[1][t],     ahi[1], bhi);
                mma_bf16(acc[1][t + 1], ahi[1], bhi + 2);
                mma_bf16(acc[0][t],     ahi[0], blo);
                mma_bf16(acc[0][t + 1], ahi[0], blo + 2);
                mma_bf16(acc[1][t],     ahi[1], blo);
                mma_bf16(acc[1][t + 1], ahi[1], blo + 2);
                mma_bf16(acc[0][t],     alo[0], bhi);
                mma_bf16(acc[0][t + 1], alo[0], bhi + 2);
                mma_bf16(acc[1][t],     alo[1], bhi);
                mma_bf16(acc[1][t + 1], alo[1], bhi + 2);
            }
        }
        if (hn) {
            storeA(av, nxt);
            CP_WAIT0();
        }
        __syncthreads();
    }

    // epilogue: bias + relu + store
    const int gq = lane >> 2, tq = lane & 3;
    #pragma unroll
    for (int mt = 0; mt < 2; mt++) {
        int m0 = bm + warp_m * 32 + mt * 16 + gq;
        #pragma unroll
        for (int t = 0; t < 8; t++) {
            int n = bn + warp_n * 64 + t * 8 + tq * 2;
            float bx = bias[n], by = bias[n + 1];
            if (m0 < N_NODES) {
                float2 o;
                o.x = fmaxf(acc[mt][t][0] + bx, 0.0f);
                o.y = fmaxf(acc[mt][t][1] + by, 0.0f);
                *(float2*)&g_hid[(size_t)m0 * NHID + n] = o;
            }
            if (m0 + 8 < N_NODES) {
                float2 o;
                o.x = fmaxf(acc[mt][t][2] + bx, 0.0f);
                o.y = fmaxf(acc[mt][t][3] + by, 0.0f);
                *(float2*)&g_hid[(size_t)(m0 + 8) * NHID + n] = o;
            }
        }
    }
}

// ---- GEMM2: h = hid@W2+b2; hA = s*h (u0); gacc = 0; out = gamma0*h --------
__global__ void __launch_bounds__(256) k_gemm2(const float* __restrict__ W2,
                                               const float* __restrict__ b2,
                                               const float* __restrict__ gamma,
                                               float* __restrict__ out) {
    __shared__ float sW[NHID * NCLASS];  // 16 KB
    const int tid = threadIdx.x;
    for (int i = tid; i < NHID * NCLASS; i += 256) sW[i] = W2[i];
    __syncthreads();
    const int node = blockIdx.x * 16 + (tid >> 4);
    const int c = tid & 15;
    const float4* hr = (const float4*)(g_hid + (size_t)node * NHID);
    float acc = 0.0f;
    #pragma unroll 8
    for (int kk = 0; kk < NHID / 4; kk++) {
        float4 h4 = hr[kk];
        int k = kk * 4;
        acc += h4.x * sW[(k + 0) * NCLASS + c];
        acc += h4.y * sW[(k + 1) * NCLASS + c];
        acc += h4.z * sW[(k + 2) * NCLASS + c];
        acc += h4.w * sW[(k + 3) * NCLASS + c];
    }
    float v = acc + b2[c];
    size_t o = (size_t)node * NCLASS + c;
    g_hA[o]   = g_s[node] * v;       // u0 = s*h
    g_gacc[o] = 0.0f;
    out[o]    = gamma[0] * v;
}

// ---- propagation (u-space): u_k[v] = s[v]^2 * sum_e u_{k-1}[row];
//      gacc += gamma_k * u_k.  No per-edge scale loads.
__global__ void __launch_bounds__(256) k_prop(const float* __restrict__ gamma,
                                              int k, int flip) {
    const int gwarp = (blockIdx.x * blockDim.x + threadIdx.x) >> 5;
    if (gwarp >= N_NODES) return;
    const float4* __restrict__ hin  = (const float4*)(flip ? g_hB : g_hA);
    float4* __restrict__       hout = (float4*)(flip ? g_hA : g_hB);
    const int lane = threadIdx.x & 31;
    const int q = lane & 3;
    const int slot = lane >> 2;
    const int start = g_colptr[gwarp];
    const int len = g_cnt_col[gwarp];
    const int* __restrict__ rows = g_csr_row + start;

    float4 acc = make_float4(0.f, 0.f, 0.f, 0.f);
    int i = slot;
    for (; i + 8 < len; i += 16) {
        int r0 = rows[i];
        int r1 = rows[i + 8];
        float4 v0 = hin[r0 * 4 + q];
        float4 v1 = hin[r1 * 4 + q];
        acc.x += v0.x + v1.x;
        acc.y += v0.y + v1.y;
        acc.z += v0.z + v1.z;
        acc.w += v0.w + v1.w;
    }
    if (i < len) {
        int r = rows[i];
        float4 v = hin[r * 4 + q];
        acc.x += v.x; acc.y += v.y; acc.z += v.z; acc.w += v.w;
    }
    #pragma unroll
    for (int o = 4; o <= 16; o <<= 1) {
        acc.x += __shfl_xor_sync(0xffffffffu, acc.x, o);
        acc.y += __shfl_xor_sync(0xffffffffu, acc.y, o);
        acc.z += __shfl_xor_sync(0xffffffffu, acc.z, o);
        acc.w += __shfl_xor_sync(0xffffffffu, acc.w, o);
    }
    if (slot == 0) {
        float sv = g_s[gwarp];
        float s2 = sv * sv;
        float4 u = make_float4(s2 * acc.x, s2 * acc.y, s2 * acc.z, s2 * acc.w);
        hout[gwarp * 4 + q] = u;
        float gk = gamma[k];
        float4* gp = (float4*)g_gacc + gwarp * 4 + q;
        float4 g4 = *gp;
        g4.x += gk * u.x; g4.y += gk * u.y; g4.z += gk * u.z; g4.w += gk * u.w;
        *gp = g4;
    }
}

// ---- final: out += gacc / s  (= gacc * sqrt(deg); 0 when deg=0) -----------
__global__ void k_final(float* __restrict__ out) {
    int t = blockIdx.x * blockDim.x + threadIdx.x;   // one float4 per thread
    if (t >= N_NODES * 4) return;
    int node = t >> 2;
    float si = g_sinv[node];
    float4 g4 = ((const float4*)g_gacc)[t];
    float4* op = (float4*)out + t;
    float4 o4 = *op;
    o4.x += si * g4.x; o4.y += si * g4.y; o4.z += si * g4.z; o4.w += si * g4.w;
    *op = o4;
}

// ---------------- launch ----------------------------------------------------
// NOTE: launch order places k_gemm1_mma 4th — the profiler captures launch #4.
extern "C" void kernel_launch(void* const* d_in, const int* in_sizes, int n_in,
                              void* d_out, int out_size) {
    const float* x     = (const float*)d_in[0];
    const int*   ei    = (const int*)  d_in[1];
    const float* W1    = (const float*)d_in[2];
    const float* b1    = (const float*)d_in[3];
    const float* W2    = (const float*)d_in[4];
    const float* b2    = (const float*)d_in[5];
    const float* gamma = (const float*)d_in[6];
    float* out = (float*)d_out;

    static bool attr_set = false;
    if (!attr_set) {
        cudaFuncSetAttribute(k_gemm1_mma, cudaFuncAttributeMaxDynamicSharedMemorySize,
                             SM1_BYTES);
        attr_set = true;
    }

    // 1-3: prep that GEMM1 needs + independent graph work
    k_wprep<<<(NHID * NFEAT + 255) / 256, 256>>>(W1);
    k_init_counts<<<(N_NODES + 255) / 256, 256>>>();
    k_hist<<<(N_EDGES + 255) / 256, 256>>>(ei);
    // 4: the kernel we want ncu to capture
    k_gemm1_mma<<<dim3(NHID / 128, (N_NODES + 127) / 128), 256, SM1_BYTES>>>(x, b1);
    // graph preprocessing (depends on hist)
    k_compute_s<<<(N_NODES + 255) / 256, 256>>>();
    k_scan1<<<NBLK_SCAN, 1024>>>();
    k_scan2<<<1, 128>>>();
    k_scan3<<<(N_NODES + 255) / 256, 256>>>();
    k_csr_fill<<<(N_EDGES + 255) / 256, 256>>>(ei);

    k_gemm2<<<N_NODES / 16, 256>>>(W2, b2, gamma, out);

    // K propagation steps (ping-pong hA/hB), u-space
    const int prop_blocks = (N_NODES * 32 + 255) / 256;
    for (int k = 1; k <= KSTEPS; k++)
        k_prop<<<prop_blocks, 256>>>(gamma, k, (k - 1) & 1);

    k_final<<<(N_NODES * 4 + 255) / 256, 256>>>(out);
}

// round 11
// speedup vs baseline: 1.7798x; 1.0424x over previous
#include <cuda_runtime.h>
#include <cuda_bf16.h>
#include <stdint.h>

#define N_NODES 100000
#define N_EDGES 3200000
#define NFEAT   512
#define NHID    256
#define NCLASS  16
#define KSTEPS  10
#define NBLK_SCAN 98   // ceil(100000/1024)

// ---------------- scratch (device globals: no allocation allowed) ----------
__device__ float g_hid[(size_t)N_NODES * NHID];     // 102.4 MB
__device__ float g_hA[(size_t)N_NODES * NCLASS];    // u ping
__device__ float g_hB[(size_t)N_NODES * NCLASS];    // u pong
__device__ float g_gacc[(size_t)N_NODES * NCLASS];  // sum_k gamma_k * u_k
__device__ int   g_cnt_row[N_NODES];
__device__ int   g_cnt_col[N_NODES];
__device__ int   g_colptr[N_NODES];
__device__ int   g_fill[N_NODES];
__device__ float g_s[N_NODES];
__device__ float g_sinv[N_NODES];                   // sqrt(deg) = 1/s (0 if deg=0)
__device__ int   g_csr_row[N_EDGES];                // 12.8 MB
__device__ int   g_bsum[NBLK_SCAN];
__device__ int   g_boff[NBLK_SCAN];
// W1 transposed + split to bf16 hi/lo: [NHID=256 rows][NFEAT=512 cols] K-major
__device__ uint4 g_W4hi[16384];                     // 256 KB
__device__ uint4 g_W4lo[16384];                     // 256 KB

// ---------------- graph preprocessing --------------------------------------
__global__ void k_init_counts() {
    int i = blockIdx.x * blockDim.x + threadIdx.x;
    if (i < N_NODES) { g_cnt_row[i] = 0; g_cnt_col[i] = 0; }
}

__global__ void k_hist(const int* __restrict__ ei) {
    int e = blockIdx.x * blockDim.x + threadIdx.x;
    if (e < N_EDGES) {
        atomicAdd(&g_cnt_row[ei[e]], 1);
        atomicAdd(&g_cnt_col[ei[N_EDGES + e]], 1);
    }
}

__global__ void k_compute_s() {
    int i = blockIdx.x * blockDim.x + threadIdx.x;
    if (i < N_NODES) {
        int d = g_cnt_row[i];
        g_s[i]    = (d > 0) ? rsqrtf((float)d) : 0.0f;
        g_sinv[i] = (d > 0) ? sqrtf((float)d)  : 0.0f;
    }
}

// parallel scan, stage 1: per-block exclusive scan + block sums
__global__ void __launch_bounds__(1024) k_scan1() {
    __shared__ int wsum[32];
    const int tid = threadIdx.x, lane = tid & 31, wid = tid >> 5;
    int i = blockIdx.x * 1024 + tid;
    int v = (i < N_NODES) ? g_cnt_col[i] : 0;
    int x = v;
    #pragma unroll
    for (int o = 1; o < 32; o <<= 1) {
        int y = __shfl_up_sync(0xffffffffu, x, o);
        if (lane >= o) x += y;
    }
    if (lane == 31) wsum[wid] = x;
    __syncthreads();
    if (wid == 0) {
        int w = wsum[lane];
        #pragma unroll
        for (int o = 1; o < 32; o <<= 1) {
            int y = __shfl_up_sync(0xffffffffu, w, o);
            if (lane >= o) w += y;
        }
        wsum[lane] = w;
    }
    __syncthreads();
    int excl = (wid ? wsum[wid - 1] : 0) + x - v;
    if (i < N_NODES) g_colptr[i] = excl;
    if (tid == 1023) g_bsum[blockIdx.x] = wsum[31];
}

// stage 2: scan the 98 block sums (single small block)
__global__ void k_scan2() {
    __shared__ int s[128];
    int tid = threadIdx.x;
    int v = (tid < NBLK_SCAN) ? g_bsum[tid] : 0;
    s[tid] = v;
    __syncthreads();
    for (int o = 1; o < 128; o <<= 1) {
        int t = (tid >= o) ? s[tid - o] : 0;
        __syncthreads();
        s[tid] += t;
        __syncthreads();
    }
    if (tid < NBLK_SCAN) g_boff[tid] = s[tid] - v;
}

// stage 3: add block offsets
__global__ void k_scan3() {
    int i = blockIdx.x * blockDim.x + threadIdx.x;
    if (i < N_NODES) {
        int v = g_colptr[i] + g_boff[i >> 10];
        g_colptr[i] = v;
        g_fill[i] = v;
    }
}

__global__ void k_csr_fill(const int* __restrict__ ei) {
    int e = blockIdx.x * blockDim.x + threadIdx.x;
    if (e < N_EDGES) {
        int r = ei[e];
        int c = ei[N_EDGES + e];
        int pos = atomicAdd(&g_fill[c], 1);
        g_csr_row[pos] = r;
    }
}

// ---------------- W1 prep: transpose + bf16 hi/lo split --------------------
__global__ void k_wprep(const float* __restrict__ W1) {
    int t = blockIdx.x * blockDim.x + threadIdx.x;
    if (t >= NHID * NFEAT) return;
    int n = t >> 9;        // 0..255
    int k = t & 511;       // 0..511
    float v = W1[(size_t)k * NHID + n];
    __nv_bfloat16 h = __float2bfloat16_rn(v);
    float lo = v - __bfloat162float(h);
    ((__nv_bfloat16*)g_W4hi)[(size_t)n * NFEAT + k] = h;
    ((__nv_bfloat16*)g_W4lo)[(size_t)n * NFEAT + k] = __float2bfloat16_rn(lo);
}

// ---------------- mma.sync / cp.async helpers ------------------------------
__device__ __forceinline__ uint32_t smem_u32(const void* p) {
    uint32_t a;
    asm("{ .reg .u64 t; cvta.to.shared.u64 t, %1; cvt.u32.u64 %0, t; }" : "=r"(a) : "l"(p));
    return a;
}
__device__ __forceinline__ void ldsm_x4(uint32_t* r, uint32_t addr) {
    asm volatile("ldmatrix.sync.aligned.m8n8.x4.shared.b16 {%0,%1,%2,%3}, [%4];"
                 : "=r"(r[0]), "=r"(r[1]), "=r"(r[2]), "=r"(r[3]) : "r"(addr));
}
__device__ __forceinline__ void mma_bf16(float* c, const uint32_t* a, const uint32_t* b) {
    asm volatile("mma.sync.aligned.m16n8k16.row.col.f32.bf16.bf16.f32 "
                 "{%0,%1,%2,%3}, {%4,%5,%6,%7}, {%8,%9}, {%0,%1,%2,%3};"
                 : "+f"(c[0]), "+f"(c[1]), "+f"(c[2]), "+f"(c[3])
                 : "r"(a[0]), "r"(a[1]), "r"(a[2]), "r"(a[3]), "r"(b[0]), "r"(b[1]));
}
__device__ __forceinline__ void cp16(uint32_t saddr, const void* g) {
    asm volatile("cp.async.cg.shared.global [%0], [%1], 16;" :: "r"(saddr), "l"(g));
}
#define CP_COMMIT() asm volatile("cp.async.commit_group;" ::: "memory")
#define CP_WAIT0()  asm volatile("cp.async.wait_group 0;" ::: "memory")

// ---- GEMM1: hid = relu(x@W1+b1), bf16x3 mma.sync, double-buffered ---------
#define APAD 40               // row stride in bf16 elems -> 80B, LDSM conflict-free
#define TSZ  (128 * APAD)     // one tile array in bf16 elems (5120)
#define SM1_BYTES (2 * 4 * TSZ * 2)   // 2 buffers x 4 arrays x 5120 x 2B = 81920

__global__ void __launch_bounds__(256, 2) k_gemm1_mma(const float* __restrict__ A,
                                                      const float* __restrict__ bias) {
    extern __shared__ __align__(16) __nv_bfloat16 dyn[];
    __nv_bfloat16* base[2] = { dyn, dyn + 4 * TSZ };

    const int tid = threadIdx.x;
    const int wid = tid >> 5, lane = tid & 31;
    const int warp_m = wid & 3;          // 4 warps in M, 32 rows each
    const int warp_n = wid >> 2;         // 2 warps in N, 64 cols each
    const int bm = blockIdx.y * 128;
    const int bn = blockIdx.x * 128;

    float acc[2][8][4];
    #pragma unroll
    for (int mt = 0; mt < 2; mt++)
        #pragma unroll
        for (int t = 0; t < 8; t++)
            #pragma unroll
            for (int j = 0; j < 4; j++) acc[mt][t][j] = 0.0f;

    const int lr16 = lane & 15;
    const uint32_t a_off = (uint32_t)(((warp_m * 32 + lr16) * APAD + (lane >> 4) * 8) * 2);
    const uint32_t b4_off = (uint32_t)(((warp_n * 64 + (lane & 7) + ((lane >> 4) * 8)) * APAD
                                        + (((lane >> 3) & 1) * 8)) * 2);
    uint32_t ahi_b[2], alo_b[2], whi_b[2], wlo_b[2];
    #pragma unroll
    for (int b = 0; b < 2; b++) {
        ahi_b[b] = smem_u32(base[b]);
        alo_b[b] = smem_u32(base[b] + TSZ);
        whi_b[b] = smem_u32(base[b] + 2 * TSZ);
        wlo_b[b] = smem_u32(base[b] + 3 * TSZ);
    }

    auto stageW = [&](int k0, int b) {
        #pragma unroll
        for (int i = 0; i < 2; i++) {
            int u = i * 256 + tid;
            int n = u >> 2, kk = u & 3;
            int gi = (bn + n) * 64 + (k0 >> 3) + kk;
            uint32_t off = (uint32_t)((n * APAD + kk * 8) * 2);
            cp16(whi_b[b] + off, &g_W4hi[gi]);
            cp16(wlo_b[b] + off, &g_W4lo[gi]);
        }
    };
    auto loadA = [&](int k0, float4* av) {
        #pragma unroll
        for (int i = 0; i < 4; i++) {
            int u = i * 256 + tid;
            int r = u >> 3, q = u & 7;
            av[i] = make_float4(0.f, 0.f, 0.f, 0.f);
            if (bm + r < N_NODES)
                av[i] = *(const float4*)(A + (size_t)(bm + r) * NFEAT + k0 + q * 4);
        }
    };
    auto storeA = [&](const float4* av, int b) {
        __nv_bfloat16* sAhi = base[b];
        __nv_bfloat16* sAlo = base[b] + TSZ;
        #pragma unroll
        for (int i = 0; i < 4; i++) {
            int u = i * 256 + tid;
            int r = u >> 3, q = u & 7;
            float4 v = av[i];
            __nv_bfloat16 h0 = __float2bfloat16_rn(v.x), h1 = __float2bfloat16_rn(v.y);
            __nv_bfloat16 h2 = __float2bfloat16_rn(v.z), h3 = __float2bfloat16_rn(v.w);
            uint2 ph, pl;
            ph.x = ((uint32_t)__bfloat16_as_ushort(h1) << 16) | __bfloat16_as_ushort(h0);
            ph.y = ((uint32_t)__bfloat16_as_ushort(h3) << 16) | __bfloat16_as_ushort(h2);
            __nv_bfloat16 l0 = __float2bfloat16_rn(v.x - __bfloat162float(h0));
            __nv_bfloat16 l1 = __float2bfloat16_rn(v.y - __bfloat162float(h1));
            __nv_bfloat16 l2 = __float2bfloat16_rn(v.z - __bfloat162float(h2));
            __nv_bfloat16 l3 = __float2bfloat16_rn(v.w - __bfloat162float(h3));
            pl.x = ((uint32_t)__bfloat16_as_ushort(l1) << 16) | __bfloat16_as_ushort(l0);
            pl.y = ((uint32_t)__bfloat16_as_ushort(l3) << 16) | __bfloat16_as_ushort(l2);
            *(uint2*)&sAhi[r * APAD + q * 4] = ph;
            *(uint2*)&sAlo[r * APAD + q * 4] = pl;
        }
    };

    float4 av[4];
    stageW(0, 0);
    CP_COMMIT();
    loadA(0, av);
    storeA(av, 0);
    CP_WAIT0();
    __syncthreads();

    for (int k0 = 0; k0 < NFEAT; k0 += 32) {
        const int buf = (k0 >> 5) & 1;
        const int nxt = buf ^ 1;
        const bool hn = (k0 + 32) < NFEAT;
        if (hn) {
            stageW(k0 + 32, nxt);
            CP_COMMIT();
            loadA(k0 + 32, av);
        }
        #pragma unroll
        for (int ks = 0; ks < 32; ks += 16) {
            uint32_t ahi[2][4], alo[2][4];
            ldsm_x4(ahi[0], ahi_b[buf] + a_off + ks * 2);
            ldsm_x4(ahi[1], ahi_b[buf] + a_off + (16 * APAD + ks) * 2);
            ldsm_x4(alo[0], alo_b[buf] + a_off + ks * 2);
            ldsm_x4(alo[1], alo_b[buf] + a_off + (16 * APAD + ks) * 2);
            #pragma unroll
            for (int t = 0; t < 8; t += 2) {
                uint32_t bhi[4], blo[4];
                ldsm_x4(bhi, whi_b[buf] + b4_off + (t * 8 * APAD + ks) * 2);
                ldsm_x4(blo, wlo_b[buf] + b4_off + (t * 8 * APAD + ks) * 2);
                mma_bf16(acc[0][t],     ahi[0], bhi);
                mma_bf16(acc[0][t + 1], ahi[0], bhi + 2);
                mma_bf16(acc[1][t],     ahi[1], bhi);
                mma_bf16(acc[1][t + 1], ahi[1], bhi + 2);
                mma_bf16(acc[0][t],     ahi[0], blo);
                mma_bf16(acc[0][t + 1], ahi[0], blo + 2);
                mma_bf16(acc[1][t],     ahi[1], blo);
                mma_bf16(acc[1][t + 1], ahi[1], blo + 2);
                mma_bf16(acc[0][t],     alo[0], bhi);
                mma_bf16(acc[0][t + 1], alo[0], bhi + 2);
                mma_bf16(acc[1][t],     alo[1], bhi);
                mma_bf16(acc[1][t + 1], alo[1], bhi + 2);
            }
        }
        if (hn) {
            storeA(av, nxt);
            CP_WAIT0();
        }
        __syncthreads();
    }

    // epilogue: bias + relu + store
    const int gq = lane >> 2, tq = lane & 3;
    #pragma unroll
    for (int mt = 0; mt < 2; mt++) {
        int m0 = bm + warp_m * 32 + mt * 16 + gq;
        #pragma unroll
        for (int t = 0; t < 8; t++) {
            int n = bn + warp_n * 64 + t * 8 + tq * 2;
            float bx = bias[n], by = bias[n + 1];
            if (m0 < N_NODES) {
                float2 o;
                o.x = fmaxf(acc[mt][t][0] + bx, 0.0f);
                o.y = fmaxf(acc[mt][t][1] + by, 0.0f);
                *(float2*)&g_hid[(size_t)m0 * NHID + n] = o;
            }
            if (m0 + 8 < N_NODES) {
                float2 o;
                o.x = fmaxf(acc[mt][t][2] + bx, 0.0f);
                o.y = fmaxf(acc[mt][t][3] + by, 0.0f);
                *(float2*)&g_hid[(size_t)(m0 + 8) * NHID + n] = o;
            }
        }
    }
}

// ---- GEMM2: h = hid@W2+b2; hA = s*h (u0); gacc = 0; out = gamma0*h --------
__global__ void __launch_bounds__(256) k_gemm2(const float* __restrict__ W2,
                                               const float* __restrict__ b2,
                                               const float* __restrict__ gamma,
                                               float* __restrict__ out) {
    __shared__ float sW[NHID * NCLASS];  // 16 KB
    const int tid = threadIdx.x;
    for (int i = tid; i < NHID * NCLASS; i += 256) sW[i] = W2[i];
    __syncthreads();
    const int node = blockIdx.x * 16 + (tid >> 4);
    const int c = tid & 15;
    const float4* hr = (const float4*)(g_hid + (size_t)node * NHID);
    float acc = 0.0f;
    #pragma unroll 8
    for (int kk = 0; kk < NHID / 4; kk++) {
        float4 h4 = hr[kk];
        int k = kk * 4;
        acc += h4.x * sW[(k + 0) * NCLASS + c];
        acc += h4.y * sW[(k + 1) * NCLASS + c];
        acc += h4.z * sW[(k + 2) * NCLASS + c];
        acc += h4.w * sW[(k + 3) * NCLASS + c];
    }
    float v = acc + b2[c];
    size_t o = (size_t)node * NCLASS + c;
    g_hA[o]   = g_s[node] * v;       // u0 = s*h
    g_gacc[o] = 0.0f;
    out[o]    = gamma[0] * v;
}

// ---- propagation (u-space): u_k[v] = s[v]^2 * sum_e u_{k-1}[row];
//      gacc += gamma_k * u_k.  No per-edge scale loads.
__global__ void __launch_bounds__(256) k_prop(const float* __restrict__ gamma,
                                              int k, int flip) {
    const int gwarp = (blockIdx.x * blockDim.x + threadIdx.x) >> 5;
    if (gwarp >= N_NODES) return;
    const float4* __restrict__ hin  = (const float4*)(flip ? g_hB : g_hA);
    float4* __restrict__       hout = (float4*)(flip ? g_hA : g_hB);
    const int lane = threadIdx.x & 31;
    const int q = lane & 3;
    const int slot = lane >> 2;
    const int start = g_colptr[gwarp];
    const int len = g_cnt_col[gwarp];
    const int* __restrict__ rows = g_csr_row + start;

    float4 acc = make_float4(0.f, 0.f, 0.f, 0.f);
    int i = slot;
    for (; i + 8 < len; i += 16) {
        int r0 = rows[i];
        int r1 = rows[i + 8];
        float4 v0 = hin[r0 * 4 + q];
        float4 v1 = hin[r1 * 4 + q];
        acc.x += v0.x + v1.x;
        acc.y += v0.y + v1.y;
        acc.z += v0.z + v1.z;
        acc.w += v0.w + v1.w;
    }
    if (i < len) {
        int r = rows[i];
        float4 v = hin[r * 4 + q];
        acc.x += v.x; acc.y += v.y; acc.z += v.z; acc.w += v.w;
    }
    #pragma unroll
    for (int o = 4; o <= 16; o <<= 1) {
        acc.x += __shfl_xor_sync(0xffffffffu, acc.x, o);
        acc.y += __shfl_xor_sync(0xffffffffu, acc.y, o);
        acc.z += __shfl_xor_sync(0xffffffffu, acc.z, o);
        acc.w += __shfl_xor_sync(0xffffffffu, acc.w, o);
    }
    if (slot == 0) {
        float sv = g_s[gwarp];
        float s2 = sv * sv;
        float4 u = make_float4(s2 * acc.x, s2 * acc.y, s2 * acc.z, s2 * acc.w);
        hout[gwarp * 4 + q] = u;
        float gk = gamma[k];
        float4* gp = (float4*)g_gacc + gwarp * 4 + q;
        float4 g4 = *gp;
        g4.x += gk * u.x; g4.y += gk * u.y; g4.z += gk * u.z; g4.w += gk * u.w;
        *gp = g4;
    }
}

// ---- final: out += gacc / s  (= gacc * sqrt(deg); 0 when deg=0) -----------
__global__ void k_final(float* __restrict__ out) {
    int t = blockIdx.x * blockDim.x + threadIdx.x;   // one float4 per thread
    if (t >= N_NODES * 4) return;
    int node = t >> 2;
    float si = g_sinv[node];
    float4 g4 = ((const float4*)g_gacc)[t];
    float4* op = (float4*)out + t;
    float4 o4 = *op;
    o4.x += si * g4.x; o4.y += si * g4.y; o4.z += si * g4.z; o4.w += si * g4.w;
    *op = o4;
}

// ---------------- launch ----------------------------------------------------
// Fork/join: graph preprocessing (atomic/L2-bound) runs on a side stream
// concurrently with GEMM1 (tensor-bound). Join (event) before k_gemm2, which
// needs both g_hid (main) and g_s (side). k_gemm1_mma stays the 4th submitted
// launch for the profiler.
extern "C" void kernel_launch(void* const* d_in, const int* in_sizes, int n_in,
                              void* d_out, int out_size) {
    const float* x     = (const float*)d_in[0];
    const int*   ei    = (const int*)  d_in[1];
    const float* W1    = (const float*)d_in[2];
    const float* b1    = (const float*)d_in[3];
    const float* W2    = (const float*)d_in[4];
    const float* b2    = (const float*)d_in[5];
    const float* gamma = (const float*)d_in[6];
    float* out = (float*)d_out;

    static cudaStream_t s2 = nullptr;
    static cudaEvent_t ev_fork = nullptr, ev_join = nullptr;
    if (!s2) {
        cudaFuncSetAttribute(k_gemm1_mma, cudaFuncAttributeMaxDynamicSharedMemorySize,
                             SM1_BYTES);
        cudaStreamCreateWithFlags(&s2, cudaStreamNonBlocking);
        cudaEventCreateWithFlags(&ev_fork, cudaEventDisableTiming);
        cudaEventCreateWithFlags(&ev_join, cudaEventDisableTiming);
    }

    // fork: side stream branches off the call stream
    cudaEventRecord(ev_fork, 0);
    cudaStreamWaitEvent(s2, ev_fork, 0);

    // main #1 + side #2,#3 (submission order keeps gemm1 at position 4)
    k_wprep<<<(NHID * NFEAT + 255) / 256, 256>>>(W1);
    k_init_counts<<<(N_NODES + 255) / 256, 256, 0, s2>>>();
    k_hist<<<(N_EDGES + 255) / 256, 256, 0, s2>>>(ei);
    // main #4: the profiled kernel
    k_gemm1_mma<<<dim3(NHID / 128, (N_NODES + 127) / 128), 256, SM1_BYTES>>>(x, b1);
    // side: rest of graph preprocessing
    k_compute_s<<<(N_NODES + 255) / 256, 256, 0, s2>>>();
    k_scan1<<<NBLK_SCAN, 1024, 0, s2>>>();
    k_scan2<<<1, 128, 0, s2>>>();
    k_scan3<<<(N_NODES + 255) / 256, 256, 0, s2>>>();
    k_csr_fill<<<(N_EDGES + 255) / 256, 256, 0, s2>>>(ei);

    // join: main waits for side chain before gemm2 (needs g_s) and prop (csr)
    cudaEventRecord(ev_join, s2);
    cudaStreamWaitEvent(0, ev_join, 0);

    k_gemm2<<<N_NODES / 16, 256>>>(W2, b2, gamma, out);

    // K propagation steps (ping-pong hA/hB), u-space
    const int prop_blocks = (N_NODES * 32 + 255) / 256;
    for (int k = 1; k <= KSTEPS; k++)
        k_prop<<<prop_blocks, 256>>>(gamma, k, (k - 1) & 1);

    k_final<<<(N_NODES * 4 + 255) / 256, 256>>>(out);
}